// round 1
// baseline (speedup 1.0000x reference)
#include <cuda_runtime.h>
#include <cstdint>

// Problem constants (fixed by the reference setup_inputs).
#define BB 16
#define CC 256
#define NN 2048

// Scratch (allocation-free rule: __device__ globals).
__device__ float g_y[(size_t)BB * CC * NN];        //  32 MB  y = Wqk @ x
__device__ float g_v[(size_t)BB * CC * NN];        //  32 MB  v = Wv @ x + bv
__device__ float g_s[(size_t)BB * NN * NN];        // 256 MB  energy -> softmax(attention)
__device__ float g_rscale[BB * NN];                //         1/((1e-9+colsum)*sqrt(C))

// ---------------------------------------------------------------------------
// Classic 128x128x8 register-tiled fp32 GEMM body (NN layout):
//   C[m][n] = sum_k A[m][k]*B[k][n]   (B has row stride NN)
// 256 threads, each computes an 8x8 micro-tile. float4 global loads.
// ---------------------------------------------------------------------------
__device__ __forceinline__ void gemm_nn_body(
    const float* __restrict__ A, int lda,
    const float* __restrict__ B,
    float* __restrict__ C,
    int K,
    const float* __restrict__ bias,       // optional, length M (row add)
    const float* __restrict__ colscale)   // optional, length NN (col mul)
{
    __shared__ float As[8 * 128];
    __shared__ float Bs[8 * 128];

    const int tid = threadIdx.x;
    const int m0 = blockIdx.y * 128;
    const int n0 = blockIdx.x * 128;

    const int arow = tid >> 1;            // 0..127
    const int acg  = (tid & 1) * 4;       // 0 or 4 (k-offset)
    const int krow = tid >> 5;            // 0..7
    const int kcol = (tid & 31) * 4;      // 0..124
    const int tr = tid >> 4;              // 0..15
    const int tc = tid & 15;              // 0..15

    float acc[8][8];
#pragma unroll
    for (int i = 0; i < 8; i++)
#pragma unroll
        for (int j = 0; j < 8; j++) acc[i][j] = 0.f;

    for (int k0 = 0; k0 < K; k0 += 8) {
        float4 av = *reinterpret_cast<const float4*>(A + (size_t)(m0 + arow) * lda + k0 + acg);
        float4 bv = *reinterpret_cast<const float4*>(B + (size_t)(k0 + krow) * NN + n0 + kcol);
        As[(acg + 0) * 128 + arow] = av.x;
        As[(acg + 1) * 128 + arow] = av.y;
        As[(acg + 2) * 128 + arow] = av.z;
        As[(acg + 3) * 128 + arow] = av.w;
        *reinterpret_cast<float4*>(Bs + krow * 128 + kcol) = bv;
        __syncthreads();

#pragma unroll
        for (int k = 0; k < 8; k++) {
            float4 a0 = *reinterpret_cast<float4*>(As + k * 128 + tr * 8);
            float4 a1 = *reinterpret_cast<float4*>(As + k * 128 + tr * 8 + 4);
            float4 b0 = *reinterpret_cast<float4*>(Bs + k * 128 + tc * 8);
            float4 b1 = *reinterpret_cast<float4*>(Bs + k * 128 + tc * 8 + 4);
            float a[8] = {a0.x, a0.y, a0.z, a0.w, a1.x, a1.y, a1.z, a1.w};
            float b[8] = {b0.x, b0.y, b0.z, b0.w, b1.x, b1.y, b1.z, b1.w};
#pragma unroll
            for (int i = 0; i < 8; i++)
#pragma unroll
                for (int j = 0; j < 8; j++)
                    acc[i][j] += a[i] * b[j];
        }
        __syncthreads();
    }

#pragma unroll
    for (int i = 0; i < 8; i++) {
        const int m = m0 + tr * 8 + i;
        const float badd = bias ? bias[m] : 0.f;
#pragma unroll
        for (int j = 0; j < 8; j++) {
            const int n = n0 + tc * 8 + j;
            float val = acc[i][j] + badd;
            if (colscale) val *= colscale[n];
            C[(size_t)m * NN + n] = val;
        }
    }
}

// --- projection: y = Wqk @ x ------------------------------------------------
__global__ __launch_bounds__(256) void proj_y_kernel(
    const float* __restrict__ W, const float* __restrict__ x)
{
    const size_t off = (size_t)blockIdx.z * CC * NN;
    gemm_nn_body(W, CC, x + off, g_y + off, CC, nullptr, nullptr);
}

// --- projection: v = Wv @ x + bv ---------------------------------------------
__global__ __launch_bounds__(256) void proj_v_kernel(
    const float* __restrict__ W, const float* __restrict__ x,
    const float* __restrict__ bias)
{
    const size_t off = (size_t)blockIdx.z * CC * NN;
    gemm_nn_body(W, CC, x + off, g_v + off, CC, bias, nullptr);
}

// --- energy: S[n][m] = sum_c y[c][n] * y[c][m]  (TN / Gram) ------------------
__global__ __launch_bounds__(256) void energy_kernel()
{
    const float* __restrict__ Y = g_y + (size_t)blockIdx.z * CC * NN;
    float* __restrict__ S = g_s + (size_t)blockIdx.z * NN * NN;

    __shared__ float As[8 * 128];
    __shared__ float Bs[8 * 128];

    const int tid = threadIdx.x;
    const int n0 = blockIdx.y * 128;   // row tile (n)
    const int m0 = blockIdx.x * 128;   // col tile (m)
    const int krow = tid >> 5;
    const int kcol = (tid & 31) * 4;
    const int tr = tid >> 4;
    const int tc = tid & 15;

    float acc[8][8];
#pragma unroll
    for (int i = 0; i < 8; i++)
#pragma unroll
        for (int j = 0; j < 8; j++) acc[i][j] = 0.f;

    for (int k0 = 0; k0 < CC; k0 += 8) {
        *reinterpret_cast<float4*>(As + krow * 128 + kcol) =
            *reinterpret_cast<const float4*>(Y + (size_t)(k0 + krow) * NN + n0 + kcol);
        *reinterpret_cast<float4*>(Bs + krow * 128 + kcol) =
            *reinterpret_cast<const float4*>(Y + (size_t)(k0 + krow) * NN + m0 + kcol);
        __syncthreads();

#pragma unroll
        for (int k = 0; k < 8; k++) {
            float4 a0 = *reinterpret_cast<float4*>(As + k * 128 + tr * 8);
            float4 a1 = *reinterpret_cast<float4*>(As + k * 128 + tr * 8 + 4);
            float4 b0 = *reinterpret_cast<float4*>(Bs + k * 128 + tc * 8);
            float4 b1 = *reinterpret_cast<float4*>(Bs + k * 128 + tc * 8 + 4);
            float a[8] = {a0.x, a0.y, a0.z, a0.w, a1.x, a1.y, a1.z, a1.w};
            float b[8] = {b0.x, b0.y, b0.z, b0.w, b1.x, b1.y, b1.z, b1.w};
#pragma unroll
            for (int i = 0; i < 8; i++)
#pragma unroll
                for (int j = 0; j < 8; j++)
                    acc[i][j] += a[i] * b[j];
        }
        __syncthreads();
    }

#pragma unroll
    for (int i = 0; i < 8; i++)
#pragma unroll
        for (int j = 0; j < 8; j++)
            S[(size_t)(n0 + tr * 8 + i) * NN + (m0 + tc * 8 + j)] = acc[i][j];
}

// --- row softmax over S (in place). One block (256 thr) per row. -------------
__global__ __launch_bounds__(256) void softmax_kernel()
{
    const int tid = threadIdx.x;
    float* __restrict__ row =
        g_s + ((size_t)blockIdx.y * NN + blockIdx.x) * NN;

    __shared__ float red[8];

    float v[8];
    float mx = -1e30f;
#pragma unroll
    for (int i = 0; i < 8; i++) {
        v[i] = row[i * 256 + tid];
        mx = fmaxf(mx, v[i]);
    }
    // block-reduce max
#pragma unroll
    for (int o = 16; o; o >>= 1) mx = fmaxf(mx, __shfl_xor_sync(0xffffffffu, mx, o));
    if ((tid & 31) == 0) red[tid >> 5] = mx;
    __syncthreads();
    mx = red[0];
#pragma unroll
    for (int i = 1; i < 8; i++) mx = fmaxf(mx, red[i]);
    __syncthreads();

    float s = 0.f;
#pragma unroll
    for (int i = 0; i < 8; i++) {
        v[i] = __expf(v[i] - mx);
        s += v[i];
    }
#pragma unroll
    for (int o = 16; o; o >>= 1) s += __shfl_xor_sync(0xffffffffu, s, o);
    if ((tid & 31) == 0) red[tid >> 5] = s;
    __syncthreads();
    s = red[0];
#pragma unroll
    for (int i = 1; i < 8; i++) s += red[i];

    const float inv = 1.f / s;
#pragma unroll
    for (int i = 0; i < 8; i++) row[i * 256 + tid] = v[i] * inv;
}

// --- column sums of softmaxed S -> rscale = 1/((1e-9+colsum)*sqrt(C)) --------
__global__ __launch_bounds__(256) void colsum_kernel()
{
    const int b = blockIdx.y;
    const int m = blockIdx.x * 256 + threadIdx.x;
    const float* __restrict__ p = g_s + (size_t)b * NN * NN + m;

    float s0 = 0.f, s1 = 0.f, s2 = 0.f, s3 = 0.f;
    for (int n = 0; n < NN; n += 4) {
        s0 += p[(size_t)(n + 0) * NN];
        s1 += p[(size_t)(n + 1) * NN];
        s2 += p[(size_t)(n + 2) * NN];
        s3 += p[(size_t)(n + 3) * NN];
    }
    const float s = (s0 + s1) + (s2 + s3);
    g_rscale[b * NN + m] = 1.0f / ((1e-9f + s) * 16.0f);  // sqrt(256)=16
}

// --- out[c][m] = (sum_n v[c][n] * s[n][m]) * rscale[m] ------------------------
__global__ __launch_bounds__(256) void out_gemm_kernel(float* __restrict__ out)
{
    const int b = blockIdx.z;
    const float* A = g_v + (size_t)b * CC * NN;
    const float* Bm = g_s + (size_t)b * NN * NN;
    const float* cs = g_rscale + (size_t)b * NN;
    float* C = out + (size_t)b * CC * NN;
    gemm_nn_body(A, NN, Bm, C, NN, nullptr, cs);
}

// ---------------------------------------------------------------------------
extern "C" void kernel_launch(void* const* d_in, const int* in_sizes, int n_in,
                              void* d_out, int out_size)
{
    const float* x   = (const float*)d_in[0];  // [16, 256, 2048]
    const float* Wqk = (const float*)d_in[1];  // [256, 256]
    const float* Wv  = (const float*)d_in[2];  // [256, 256]
    const float* bv  = (const float*)d_in[3];  // [256]
    float* out = (float*)d_out;                // [16, 256, 2048]

    const dim3 blk(256);

    // Projections: grid (N/128, C/128, B)
    proj_y_kernel<<<dim3(NN / 128, CC / 128, BB), blk>>>(Wqk, x);
    proj_v_kernel<<<dim3(NN / 128, CC / 128, BB), blk>>>(Wv, x, bv);

    // Energy Gram GEMM: grid (N/128, N/128, B)
    energy_kernel<<<dim3(NN / 128, NN / 128, BB), blk>>>();

    // Row softmax: one block per row
    softmax_kernel<<<dim3(NN, BB), blk>>>();

    // Column sums -> rscale
    colsum_kernel<<<dim3(NN / 256, BB), blk>>>();

    // Output GEMM with column-scale epilogue
    out_gemm_kernel<<<dim3(NN / 128, CC / 128, BB), blk>>>(out);
}

// round 3
// speedup vs baseline: 1.8587x; 1.8587x over previous
#include <cuda_runtime.h>
#include <cuda_bf16.h>
#include <cstdint>

#define BB 16
#define CC 256
#define NN 2048

// ---------------------------------------------------------------------------
// Scratch (__device__ globals; no allocation allowed)
// ---------------------------------------------------------------------------
__device__ __nv_bfloat16 g_yt_hi[(size_t)BB * NN * CC];  // y^T [b][n][c]
__device__ __nv_bfloat16 g_yt_lo[(size_t)BB * NN * CC];
__device__ __nv_bfloat16 g_v_hi[(size_t)BB * CC * NN];   // v   [b][c][n]
__device__ __nv_bfloat16 g_v_lo[(size_t)BB * CC * NN];
__device__ __nv_bfloat16 g_at_hi[(size_t)BB * NN * NN];  // attention^T [b][m][n]
__device__ __nv_bfloat16 g_at_lo[(size_t)BB * NN * NN];
__device__ float g_s[(size_t)BB * NN * NN];              // energy -> softmax (in place)
__device__ float g_rscale[BB * NN];                      // 1/((1e-9+colsum)*16)

// ---------------------------------------------------------------------------
// Baseline-PTX helpers (no 'a' features: mma.sync / ldmatrix / cp.async only)
// ---------------------------------------------------------------------------
__device__ __forceinline__ uint32_t smem_to_u32(const void* smem_ptr) {
    uint32_t addr;
    asm("{ .reg .u64 tmp; cvta.to.shared.u64 tmp, %1; cvt.u32.u64 %0, tmp; }"
        : "=r"(addr) : "l"(smem_ptr));
    return addr;
}

__device__ __forceinline__ void ldsm_x4(uint32_t* r, uint32_t addr) {
    asm volatile("ldmatrix.sync.aligned.m8n8.x4.shared.b16 {%0,%1,%2,%3}, [%4];"
                 : "=r"(r[0]), "=r"(r[1]), "=r"(r[2]), "=r"(r[3]) : "r"(addr));
}

__device__ __forceinline__ void mma_bf16(float* d, const uint32_t* a, const uint32_t* b) {
    asm volatile(
        "mma.sync.aligned.m16n8k16.row.col.f32.bf16.bf16.f32 "
        "{%0,%1,%2,%3},{%4,%5,%6,%7},{%8,%9},{%0,%1,%2,%3};"
        : "+f"(d[0]), "+f"(d[1]), "+f"(d[2]), "+f"(d[3])
        : "r"(a[0]), "r"(a[1]), "r"(a[2]), "r"(a[3]), "r"(b[0]), "r"(b[1]));
}

__device__ __forceinline__ void cp16(uint32_t saddr, const void* g) {
    asm volatile("cp.async.cg.shared.global [%0], [%1], 16;" :: "r"(saddr), "l"(g));
}
__device__ __forceinline__ void cp_commit() {
    asm volatile("cp.async.commit_group;" ::: "memory");
}
template <int N> __device__ __forceinline__ void cp_wait() {
    asm volatile("cp.async.wait_group %0;" :: "n"(N) : "memory");
}

__device__ __forceinline__ void split_bf16(float f, __nv_bfloat16& h, __nv_bfloat16& l) {
    h = __float2bfloat16(f);
    l = __float2bfloat16(f - __bfloat162float(h));
}

// ---------------------------------------------------------------------------
// Warp-MMA GEMM core: D[128,128] = sum_k (Ah+Al)[r][k] * (Bh+Bl)[c][k]
// (NT: both operands K-contiguous rows). 256 thr, warp tile 64x32 (2x4 warps),
// K staged 32, 2-stage cp.async pipeline. Split-3: AhBh + AhBl + AlBh.
// ---------------------------------------------------------------------------
#define TSTRIDE 80          // smem bytes per row (32 bf16 = 64B, padded to 80)
#define TILE_BYTES (128 * TSTRIDE)
#define STAGE_BYTES (4 * TILE_BYTES)     // Ah, Al, Bh, Bl
#define SMEM_MMA (2 * STAGE_BYTES)       // 81920

__device__ __forceinline__ void fill_stage(
    uint32_t sb, int stage, int k0,
    const __nv_bfloat16* __restrict__ Ah, const __nv_bfloat16* __restrict__ Al, int sA,
    const __nv_bfloat16* __restrict__ Bh, const __nv_bfloat16* __restrict__ Bl, int sB)
{
    const int tid = threadIdx.x;
    const int row = tid >> 1;
    const int half = tid & 1;
    const uint32_t s0 = sb + stage * STAGE_BYTES + row * TSTRIDE + half * 32;
    const int go = k0 + half * 16;
    const __nv_bfloat16* pAh = Ah + (size_t)row * sA + go;
    const __nv_bfloat16* pAl = Al + (size_t)row * sA + go;
    const __nv_bfloat16* pBh = Bh + (size_t)row * sB + go;
    const __nv_bfloat16* pBl = Bl + (size_t)row * sB + go;
    cp16(s0 + 0 * TILE_BYTES, pAh);      cp16(s0 + 0 * TILE_BYTES + 16, pAh + 8);
    cp16(s0 + 1 * TILE_BYTES, pAl);      cp16(s0 + 1 * TILE_BYTES + 16, pAl + 8);
    cp16(s0 + 2 * TILE_BYTES, pBh);      cp16(s0 + 2 * TILE_BYTES + 16, pBh + 8);
    cp16(s0 + 3 * TILE_BYTES, pBl);      cp16(s0 + 3 * TILE_BYTES + 16, pBl + 8);
}

__device__ __forceinline__ void compute_stage(uint32_t sb, int stage, float acc[4][4][4])
{
    const int lane = threadIdx.x & 31;
    const int wid = threadIdx.x >> 5;
    const int wm = wid >> 2;     // 0..1
    const int wn = wid & 3;      // 0..3
    const uint32_t st = sb + stage * STAGE_BYTES;
    // ldmatrix lane address offset: lanes 0-7 rows 0-7 (k lo-half), 8-15 rows 8-15,
    // 16-23 rows 0-7 (k hi-half), 24-31 rows 8-15.
    const uint32_t laneoff =
        (uint32_t)(((lane & 7) + ((lane >> 3) & 1) * 8) * TSTRIDE + (lane >> 4) * 16);

#pragma unroll
    for (int k16 = 0; k16 < 2; k16++) {
        const uint32_t kb = (uint32_t)(k16 * 32);
        uint32_t a_hi[4][4], a_lo[4][4], b_hi[4][2], b_lo[4][2];
#pragma unroll
        for (int mt = 0; mt < 4; mt++) {
            uint32_t ad = st + (uint32_t)((wm * 64 + mt * 16) * TSTRIDE) + kb + laneoff;
            ldsm_x4(a_hi[mt], ad);
            ldsm_x4(a_lo[mt], ad + TILE_BYTES);
        }
#pragma unroll
        for (int np = 0; np < 2; np++) {
            uint32_t bd = st + 2 * TILE_BYTES +
                          (uint32_t)((wn * 32 + np * 16) * TSTRIDE) + kb + laneoff;
            uint32_t r[4], rl[4];
            ldsm_x4(r, bd);
            ldsm_x4(rl, bd + TILE_BYTES);
            b_hi[np * 2 + 0][0] = r[0];  b_hi[np * 2 + 0][1] = r[2];
            b_hi[np * 2 + 1][0] = r[1];  b_hi[np * 2 + 1][1] = r[3];
            b_lo[np * 2 + 0][0] = rl[0]; b_lo[np * 2 + 0][1] = rl[2];
            b_lo[np * 2 + 1][0] = rl[1]; b_lo[np * 2 + 1][1] = rl[3];
        }
#pragma unroll
        for (int mt = 0; mt < 4; mt++)
#pragma unroll
            for (int nt = 0; nt < 4; nt++) {
                mma_bf16(acc[mt][nt], a_hi[mt], b_hi[nt]);
                mma_bf16(acc[mt][nt], a_hi[mt], b_lo[nt]);
                mma_bf16(acc[mt][nt], a_lo[mt], b_hi[nt]);
            }
    }
}

__device__ __forceinline__ void mma_core(
    const __nv_bfloat16* Ah, const __nv_bfloat16* Al, int sA,
    const __nv_bfloat16* Bh, const __nv_bfloat16* Bl, int sB,
    float* D, int sD, const float* colscale, int K)
{
    extern __shared__ char smem[];
    const uint32_t sb = smem_to_u32(smem);

    float acc[4][4][4];
#pragma unroll
    for (int mt = 0; mt < 4; mt++)
#pragma unroll
        for (int nt = 0; nt < 4; nt++)
#pragma unroll
            for (int q = 0; q < 4; q++) acc[mt][nt][q] = 0.f;

    const int S = K / 32;
    fill_stage(sb, 0, 0, Ah, Al, sA, Bh, Bl, sB);
    cp_commit();

    for (int s = 0; s < S; s++) {
        if (s + 1 < S) {
            fill_stage(sb, (s + 1) & 1, (s + 1) * 32, Ah, Al, sA, Bh, Bl, sB);
            cp_commit();
            cp_wait<1>();
        } else {
            cp_wait<0>();
        }
        __syncthreads();
        compute_stage(sb, s & 1, acc);
        __syncthreads();
    }

    const int lane = threadIdx.x & 31;
    const int wid = threadIdx.x >> 5;
    const int wm = wid >> 2, wn = wid & 3;
    const int r0 = wm * 64 + (lane >> 2);
    const int c0 = wn * 32 + (lane & 3) * 2;
#pragma unroll
    for (int mt = 0; mt < 4; mt++)
#pragma unroll
        for (int nt = 0; nt < 4; nt++) {
            const int row = r0 + mt * 16;
            const int col = c0 + nt * 8;
            float s0 = 1.f, s1 = 1.f;
            if (colscale) { s0 = colscale[col]; s1 = colscale[col + 1]; }
            *reinterpret_cast<float2*>(D + (size_t)row * sD + col) =
                make_float2(acc[mt][nt][0] * s0, acc[mt][nt][1] * s1);
            *reinterpret_cast<float2*>(D + (size_t)(row + 8) * sD + col) =
                make_float2(acc[mt][nt][2] * s0, acc[mt][nt][3] * s1);
        }
}

// --- energy: S[n][m] = sum_c yt[n][c] * yt[m][c] ------------------------------
__global__ __launch_bounds__(256, 1) void energy_mma_kernel()
{
    const int b = blockIdx.z;
    const int m0 = blockIdx.x * 128;
    const int n0 = blockIdx.y * 128;
    const __nv_bfloat16* baseH = g_yt_hi + (size_t)b * NN * CC;
    const __nv_bfloat16* baseL = g_yt_lo + (size_t)b * NN * CC;
    float* D = g_s + (size_t)b * NN * NN + (size_t)n0 * NN + m0;
    mma_core(baseH + (size_t)n0 * CC, baseL + (size_t)n0 * CC, CC,
             baseH + (size_t)m0 * CC, baseL + (size_t)m0 * CC, CC,
             D, NN, nullptr, CC);
}

// --- out[c][m] = (sum_n v[c][n] * at[m][n]) * rscale[m] ------------------------
__global__ __launch_bounds__(256, 1) void out_mma_kernel(float* __restrict__ out)
{
    const int b = blockIdx.z;
    const int m0 = blockIdx.x * 128;
    const int c0 = blockIdx.y * 128;
    const __nv_bfloat16* vH = g_v_hi + (size_t)b * CC * NN + (size_t)c0 * NN;
    const __nv_bfloat16* vL = g_v_lo + (size_t)b * CC * NN + (size_t)c0 * NN;
    const __nv_bfloat16* aH = g_at_hi + (size_t)b * NN * NN + (size_t)m0 * NN;
    const __nv_bfloat16* aL = g_at_lo + (size_t)b * NN * NN + (size_t)m0 * NN;
    float* D = out + (size_t)b * CC * NN + (size_t)c0 * NN + m0;
    mma_core(vH, vL, NN, aH, aL, NN, D, NN, g_rscale + (size_t)b * NN + m0, NN);
}

// ---------------------------------------------------------------------------
// fp32 projection GEMMs (128x128x8 register tiled), epilogue emits bf16 hi/lo.
// ---------------------------------------------------------------------------
__global__ __launch_bounds__(256) void proj_y_kernel(
    const float* __restrict__ W, const float* __restrict__ x)
{
    __shared__ float As[8 * 128];
    __shared__ float Bs[8 * 128];

    const int b = blockIdx.z;
    const int tid = threadIdx.x;
    const int m0 = blockIdx.y * 128;      // channel o
    const int n0 = blockIdx.x * 128;      // position n
    const float* B = x + (size_t)b * CC * NN;

    const int arow = tid >> 1;
    const int acg  = (tid & 1) * 4;
    const int krow = tid >> 5;
    const int kcol = (tid & 31) * 4;
    const int tr = tid >> 4;
    const int tc = tid & 15;

    float acc[8][8];
#pragma unroll
    for (int i = 0; i < 8; i++)
#pragma unroll
        for (int j = 0; j < 8; j++) acc[i][j] = 0.f;

    for (int k0 = 0; k0 < CC; k0 += 8) {
        float4 av = *reinterpret_cast<const float4*>(W + (size_t)(m0 + arow) * CC + k0 + acg);
        float4 bvv = *reinterpret_cast<const float4*>(B + (size_t)(k0 + krow) * NN + n0 + kcol);
        As[(acg + 0) * 128 + arow] = av.x;
        As[(acg + 1) * 128 + arow] = av.y;
        As[(acg + 2) * 128 + arow] = av.z;
        As[(acg + 3) * 128 + arow] = av.w;
        *reinterpret_cast<float4*>(Bs + krow * 128 + kcol) = bvv;
        __syncthreads();
#pragma unroll
        for (int k = 0; k < 8; k++) {
            float4 a0 = *reinterpret_cast<float4*>(As + k * 128 + tr * 8);
            float4 a1 = *reinterpret_cast<float4*>(As + k * 128 + tr * 8 + 4);
            float4 b0 = *reinterpret_cast<float4*>(Bs + k * 128 + tc * 8);
            float4 b1 = *reinterpret_cast<float4*>(Bs + k * 128 + tc * 8 + 4);
            float a[8] = {a0.x, a0.y, a0.z, a0.w, a1.x, a1.y, a1.z, a1.w};
            float bb[8] = {b0.x, b0.y, b0.z, b0.w, b1.x, b1.y, b1.z, b1.w};
#pragma unroll
            for (int i = 0; i < 8; i++)
#pragma unroll
                for (int j = 0; j < 8; j++)
                    acc[i][j] += a[i] * bb[j];
        }
        __syncthreads();
    }

    // epilogue: yt[n][o] hi/lo (transposed), 8 consecutive o per 16B store
    const size_t ytb = (size_t)b * NN * CC;
#pragma unroll
    for (int j = 0; j < 8; j++) {
        const int n = n0 + tc * 8 + j;
        __align__(16) __nv_bfloat16 hi8[8], lo8[8];
#pragma unroll
        for (int i = 0; i < 8; i++) split_bf16(acc[i][j], hi8[i], lo8[i]);
        const size_t off = ytb + (size_t)n * CC + m0 + tr * 8;
        *reinterpret_cast<uint4*>(g_yt_hi + off) = *reinterpret_cast<uint4*>(hi8);
        *reinterpret_cast<uint4*>(g_yt_lo + off) = *reinterpret_cast<uint4*>(lo8);
    }
}

__global__ __launch_bounds__(256) void proj_v_kernel(
    const float* __restrict__ W, const float* __restrict__ x,
    const float* __restrict__ bias)
{
    __shared__ float As[8 * 128];
    __shared__ float Bs[8 * 128];

    const int b = blockIdx.z;
    const int tid = threadIdx.x;
    const int m0 = blockIdx.y * 128;
    const int n0 = blockIdx.x * 128;
    const float* B = x + (size_t)b * CC * NN;

    const int arow = tid >> 1;
    const int acg  = (tid & 1) * 4;
    const int krow = tid >> 5;
    const int kcol = (tid & 31) * 4;
    const int tr = tid >> 4;
    const int tc = tid & 15;

    float acc[8][8];
#pragma unroll
    for (int i = 0; i < 8; i++)
#pragma unroll
        for (int j = 0; j < 8; j++) acc[i][j] = 0.f;

    for (int k0 = 0; k0 < CC; k0 += 8) {
        float4 av = *reinterpret_cast<const float4*>(W + (size_t)(m0 + arow) * CC + k0 + acg);
        float4 bvv = *reinterpret_cast<const float4*>(B + (size_t)(k0 + krow) * NN + n0 + kcol);
        As[(acg + 0) * 128 + arow] = av.x;
        As[(acg + 1) * 128 + arow] = av.y;
        As[(acg + 2) * 128 + arow] = av.z;
        As[(acg + 3) * 128 + arow] = av.w;
        *reinterpret_cast<float4*>(Bs + krow * 128 + kcol) = bvv;
        __syncthreads();
#pragma unroll
        for (int k = 0; k < 8; k++) {
            float4 a0 = *reinterpret_cast<float4*>(As + k * 128 + tr * 8);
            float4 a1 = *reinterpret_cast<float4*>(As + k * 128 + tr * 8 + 4);
            float4 b0 = *reinterpret_cast<float4*>(Bs + k * 128 + tc * 8);
            float4 b1 = *reinterpret_cast<float4*>(Bs + k * 128 + tc * 8 + 4);
            float a[8] = {a0.x, a0.y, a0.z, a0.w, a1.x, a1.y, a1.z, a1.w};
            float bb[8] = {b0.x, b0.y, b0.z, b0.w, b1.x, b1.y, b1.z, b1.w};
#pragma unroll
            for (int i = 0; i < 8; i++)
#pragma unroll
                for (int j = 0; j < 8; j++)
                    acc[i][j] += a[i] * bb[j];
        }
        __syncthreads();
    }

    const size_t vb = (size_t)b * CC * NN;
#pragma unroll
    for (int i = 0; i < 8; i++) {
        const int c = m0 + tr * 8 + i;
        const float badd = bias[c];
        __align__(16) __nv_bfloat16 hi8[8], lo8[8];
#pragma unroll
        for (int j = 0; j < 8; j++) split_bf16(acc[i][j] + badd, hi8[j], lo8[j]);
        const size_t off = vb + (size_t)c * NN + n0 + tc * 8;
        *reinterpret_cast<uint4*>(g_v_hi + off) = *reinterpret_cast<uint4*>(hi8);
        *reinterpret_cast<uint4*>(g_v_lo + off) = *reinterpret_cast<uint4*>(lo8);
    }
}

// --- row softmax over S (in place). One block per row. -----------------------
__global__ __launch_bounds__(256) void softmax_kernel()
{
    const int tid = threadIdx.x;
    float* __restrict__ row = g_s + ((size_t)blockIdx.y * NN + blockIdx.x) * NN;

    __shared__ float red[8];

    float v[8];
    float mx = -1e30f;
#pragma unroll
    for (int i = 0; i < 8; i++) {
        v[i] = row[i * 256 + tid];
        mx = fmaxf(mx, v[i]);
    }
#pragma unroll
    for (int o = 16; o; o >>= 1) mx = fmaxf(mx, __shfl_xor_sync(0xffffffffu, mx, o));
    if ((tid & 31) == 0) red[tid >> 5] = mx;
    __syncthreads();
    mx = red[0];
#pragma unroll
    for (int i = 1; i < 8; i++) mx = fmaxf(mx, red[i]);
    __syncthreads();

    float s = 0.f;
#pragma unroll
    for (int i = 0; i < 8; i++) {
        v[i] = __expf(v[i] - mx);
        s += v[i];
    }
#pragma unroll
    for (int o = 16; o; o >>= 1) s += __shfl_xor_sync(0xffffffffu, s, o);
    if ((tid & 31) == 0) red[tid >> 5] = s;
    __syncthreads();
    s = red[0];
#pragma unroll
    for (int i = 1; i < 8; i++) s += red[i];

    const float inv = 1.f / s;
#pragma unroll
    for (int i = 0; i < 8; i++) row[i * 256 + tid] = v[i] * inv;
}

// --- transpose + bf16 split: at[m][n] = softmax(S)[n][m] ----------------------
__global__ __launch_bounds__(256) void transpose_split_kernel()
{
    __shared__ float t[64][65];
    const int b = blockIdx.z;
    const int m0 = blockIdx.x * 64;
    const int n0 = blockIdx.y * 64;
    const float* S = g_s + (size_t)b * NN * NN;

    const int r = threadIdx.x >> 4;          // 0..15
    const int c4 = (threadIdx.x & 15) * 4;   // 0..60

#pragma unroll
    for (int rr = 0; rr < 4; rr++) {
        const int row = r + rr * 16;
        float4 v = *reinterpret_cast<const float4*>(S + (size_t)(n0 + row) * NN + m0 + c4);
        t[row][c4 + 0] = v.x;
        t[row][c4 + 1] = v.y;
        t[row][c4 + 2] = v.z;
        t[row][c4 + 3] = v.w;
    }
    __syncthreads();

    const size_t ob = (size_t)b * NN * NN;
#pragma unroll
    for (int rr = 0; rr < 4; rr++) {
        const int row = r + rr * 16;   // m - m0
        __align__(8) __nv_bfloat16 hi4[4], lo4[4];
#pragma unroll
        for (int q = 0; q < 4; q++) split_bf16(t[c4 + q][row], hi4[q], lo4[q]);
        const size_t off = ob + (size_t)(m0 + row) * NN + n0 + c4;
        *reinterpret_cast<uint2*>(g_at_hi + off) = *reinterpret_cast<uint2*>(hi4);
        *reinterpret_cast<uint2*>(g_at_lo + off) = *reinterpret_cast<uint2*>(lo4);
    }
}

// --- colsum over n (rows of at) -> rscale ------------------------------------
__global__ __launch_bounds__(256) void colsum_kernel()
{
    const int b = blockIdx.y;
    const int m = blockIdx.x;
    const int tid = threadIdx.x;
    const __nv_bfloat16* row = g_at_hi + (size_t)b * NN * NN + (size_t)m * NN;

    __shared__ float red[8];

    uint4 u = *reinterpret_cast<const uint4*>(row + tid * 8);
    const __nv_bfloat162* p = reinterpret_cast<const __nv_bfloat162*>(&u);
    float s = 0.f;
#pragma unroll
    for (int q = 0; q < 4; q++) {
        float2 f = __bfloat1622float2(p[q]);
        s += f.x + f.y;
    }
#pragma unroll
    for (int o = 16; o; o >>= 1) s += __shfl_xor_sync(0xffffffffu, s, o);
    if ((tid & 31) == 0) red[tid >> 5] = s;
    __syncthreads();
    if (tid == 0) {
        float tot = 0.f;
#pragma unroll
        for (int i = 0; i < 8; i++) tot += red[i];
        g_rscale[b * NN + m] = 1.0f / ((1e-9f + tot) * 16.0f);
    }
}

// ---------------------------------------------------------------------------
extern "C" void kernel_launch(void* const* d_in, const int* in_sizes, int n_in,
                              void* d_out, int out_size)
{
    const float* x   = (const float*)d_in[0];
    const float* Wqk = (const float*)d_in[1];
    const float* Wv  = (const float*)d_in[2];
    const float* bv  = (const float*)d_in[3];
    float* out = (float*)d_out;

    cudaFuncSetAttribute(energy_mma_kernel, cudaFuncAttributeMaxDynamicSharedMemorySize, SMEM_MMA);
    cudaFuncSetAttribute(out_mma_kernel, cudaFuncAttributeMaxDynamicSharedMemorySize, SMEM_MMA);

    proj_y_kernel<<<dim3(NN / 128, CC / 128, BB), 256>>>(Wqk, x);
    proj_v_kernel<<<dim3(NN / 128, CC / 128, BB), 256>>>(Wv, x, bv);

    energy_mma_kernel<<<dim3(NN / 128, NN / 128, BB), 256, SMEM_MMA>>>();

    softmax_kernel<<<dim3(NN, BB), 256>>>();

    transpose_split_kernel<<<dim3(NN / 64, NN / 64, BB), 256>>>();

    colsum_kernel<<<dim3(NN, BB), 256>>>();

    out_mma_kernel<<<dim3(NN / 128, CC / 128, BB), 256, SMEM_MMA>>>(out);
}

// round 4
// speedup vs baseline: 2.1668x; 1.1658x over previous
#include <cuda_runtime.h>
#include <cuda_bf16.h>
#include <cstdint>

#define BB 16
#define CC 256
#define NN 2048

// ---------------------------------------------------------------------------
// Scratch (__device__ globals; no allocation allowed)
// ---------------------------------------------------------------------------
__device__ __nv_bfloat16 g_xt_hi[(size_t)BB * NN * CC];  // x^T [b][n][c]
__device__ __nv_bfloat16 g_xt_lo[(size_t)BB * NN * CC];
__device__ __nv_bfloat16 g_wqk_hi[CC * CC];
__device__ __nv_bfloat16 g_wqk_lo[CC * CC];
__device__ __nv_bfloat16 g_wv_hi[CC * CC];
__device__ __nv_bfloat16 g_wv_lo[CC * CC];
__device__ __nv_bfloat16 g_yt_hi[(size_t)BB * NN * CC];  // y^T [b][n][o]
__device__ __nv_bfloat16 g_yt_lo[(size_t)BB * NN * CC];
__device__ __nv_bfloat16 g_v_hi[(size_t)BB * CC * NN];   // v   [b][c][n]
__device__ __nv_bfloat16 g_v_lo[(size_t)BB * CC * NN];
__device__ __nv_bfloat16 g_at_hi[(size_t)BB * NN * NN];  // attention^T [b][m][n]
__device__ __nv_bfloat16 g_at_lo[(size_t)BB * NN * NN];
__device__ float g_s[(size_t)BB * NN * NN];              // energy -> softmax (in place)
__device__ float g_rscale[BB * NN];                      // 1/((1e-9+colsum)*16)

// ---------------------------------------------------------------------------
// Baseline-PTX helpers (no 'a' features)
// ---------------------------------------------------------------------------
__device__ __forceinline__ uint32_t smem_to_u32(const void* smem_ptr) {
    uint32_t addr;
    asm("{ .reg .u64 tmp; cvta.to.shared.u64 tmp, %1; cvt.u32.u64 %0, tmp; }"
        : "=r"(addr) : "l"(smem_ptr));
    return addr;
}

__device__ __forceinline__ void ldsm_x4(uint32_t* r, uint32_t addr) {
    asm volatile("ldmatrix.sync.aligned.m8n8.x4.shared.b16 {%0,%1,%2,%3}, [%4];"
                 : "=r"(r[0]), "=r"(r[1]), "=r"(r[2]), "=r"(r[3]) : "r"(addr));
}

__device__ __forceinline__ void mma_bf16(float* d, const uint32_t* a, const uint32_t* b) {
    asm volatile(
        "mma.sync.aligned.m16n8k16.row.col.f32.bf16.bf16.f32 "
        "{%0,%1,%2,%3},{%4,%5,%6,%7},{%8,%9},{%0,%1,%2,%3};"
        : "+f"(d[0]), "+f"(d[1]), "+f"(d[2]), "+f"(d[3])
        : "r"(a[0]), "r"(a[1]), "r"(a[2]), "r"(a[3]), "r"(b[0]), "r"(b[1]));
}

__device__ __forceinline__ void cp16(uint32_t saddr, const void* g) {
    asm volatile("cp.async.cg.shared.global [%0], [%1], 16;" :: "r"(saddr), "l"(g));
}
__device__ __forceinline__ void cp_commit() {
    asm volatile("cp.async.commit_group;" ::: "memory");
}
template <int N> __device__ __forceinline__ void cp_wait() {
    asm volatile("cp.async.wait_group %0;" :: "n"(N) : "memory");
}

__device__ __forceinline__ void split_bf16(float f, __nv_bfloat16& h, __nv_bfloat16& l) {
    h = __float2bfloat16(f);
    l = __float2bfloat16(f - __bfloat162float(h));
}

// ---------------------------------------------------------------------------
// Warp-MMA GEMM core: acc[128,128] = sum_k (Ah+Al)[r][k]*(Bh+Bl)[c][k]
// (NT: both operands K-contiguous rows). 256 thr, warp tile 64x32 (2x4 warps),
// K staged 32, 2-stage cp.async pipeline. Split-3: AhBh + AhBl + AlBh.
// ---------------------------------------------------------------------------
#define TSTRIDE 80
#define TILE_BYTES (128 * TSTRIDE)
#define STAGE_BYTES (4 * TILE_BYTES)
#define SMEM_MMA (2 * STAGE_BYTES)      // 81920

__device__ __forceinline__ void fill_stage(
    uint32_t sb, int stage, int k0,
    const __nv_bfloat16* __restrict__ Ah, const __nv_bfloat16* __restrict__ Al, int sA,
    const __nv_bfloat16* __restrict__ Bh, const __nv_bfloat16* __restrict__ Bl, int sB)
{
    const int tid = threadIdx.x;
    const int row = tid >> 1;
    const int half = tid & 1;
    const uint32_t s0 = sb + stage * STAGE_BYTES + row * TSTRIDE + half * 32;
    const int go = k0 + half * 16;
    const __nv_bfloat16* pAh = Ah + (size_t)row * sA + go;
    const __nv_bfloat16* pAl = Al + (size_t)row * sA + go;
    const __nv_bfloat16* pBh = Bh + (size_t)row * sB + go;
    const __nv_bfloat16* pBl = Bl + (size_t)row * sB + go;
    cp16(s0 + 0 * TILE_BYTES, pAh);      cp16(s0 + 0 * TILE_BYTES + 16, pAh + 8);
    cp16(s0 + 1 * TILE_BYTES, pAl);      cp16(s0 + 1 * TILE_BYTES + 16, pAl + 8);
    cp16(s0 + 2 * TILE_BYTES, pBh);      cp16(s0 + 2 * TILE_BYTES + 16, pBh + 8);
    cp16(s0 + 3 * TILE_BYTES, pBl);      cp16(s0 + 3 * TILE_BYTES + 16, pBl + 8);
}

__device__ __forceinline__ void compute_stage(uint32_t sb, int stage, float acc[4][4][4])
{
    const int lane = threadIdx.x & 31;
    const int wid = threadIdx.x >> 5;
    const int wm = wid >> 2;
    const int wn = wid & 3;
    const uint32_t st = sb + stage * STAGE_BYTES;
    const uint32_t laneoff =
        (uint32_t)(((lane & 7) + ((lane >> 3) & 1) * 8) * TSTRIDE + (lane >> 4) * 16);

#pragma unroll
    for (int k16 = 0; k16 < 2; k16++) {
        const uint32_t kb = (uint32_t)(k16 * 32);
        uint32_t a_hi[4][4], a_lo[4][4], b_hi[4][2], b_lo[4][2];
#pragma unroll
        for (int mt = 0; mt < 4; mt++) {
            uint32_t ad = st + (uint32_t)((wm * 64 + mt * 16) * TSTRIDE) + kb + laneoff;
            ldsm_x4(a_hi[mt], ad);
            ldsm_x4(a_lo[mt], ad + TILE_BYTES);
        }
#pragma unroll
        for (int np = 0; np < 2; np++) {
            uint32_t bd = st + 2 * TILE_BYTES +
                          (uint32_t)((wn * 32 + np * 16) * TSTRIDE) + kb + laneoff;
            uint32_t r[4], rl[4];
            ldsm_x4(r, bd);
            ldsm_x4(rl, bd + TILE_BYTES);
            b_hi[np * 2 + 0][0] = r[0];  b_hi[np * 2 + 0][1] = r[2];
            b_hi[np * 2 + 1][0] = r[1];  b_hi[np * 2 + 1][1] = r[3];
            b_lo[np * 2 + 0][0] = rl[0]; b_lo[np * 2 + 0][1] = rl[2];
            b_lo[np * 2 + 1][0] = rl[1]; b_lo[np * 2 + 1][1] = rl[3];
        }
#pragma unroll
        for (int mt = 0; mt < 4; mt++)
#pragma unroll
            for (int nt = 0; nt < 4; nt++) {
                mma_bf16(acc[mt][nt], a_hi[mt], b_hi[nt]);
                mma_bf16(acc[mt][nt], a_hi[mt], b_lo[nt]);
                mma_bf16(acc[mt][nt], a_lo[mt], b_hi[nt]);
            }
    }
}

__device__ __forceinline__ void mma_compute(
    uint32_t sb,
    const __nv_bfloat16* Ah, const __nv_bfloat16* Al, int sA,
    const __nv_bfloat16* Bh, const __nv_bfloat16* Bl, int sB,
    int K, float acc[4][4][4])
{
#pragma unroll
    for (int mt = 0; mt < 4; mt++)
#pragma unroll
        for (int nt = 0; nt < 4; nt++)
#pragma unroll
            for (int q = 0; q < 4; q++) acc[mt][nt][q] = 0.f;

    const int S = K / 32;
    fill_stage(sb, 0, 0, Ah, Al, sA, Bh, Bl, sB);
    cp_commit();

    for (int s = 0; s < S; s++) {
        if (s + 1 < S) {
            fill_stage(sb, (s + 1) & 1, (s + 1) * 32, Ah, Al, sA, Bh, Bl, sB);
            cp_commit();
            cp_wait<1>();
        } else {
            cp_wait<0>();
        }
        __syncthreads();
        compute_stage(sb, s & 1, acc);
        __syncthreads();
    }
}

// ---------------------------------------------------------------------------
// GEMM kernels
// ---------------------------------------------------------------------------

// energy (symmetric): triangular tile enumeration, mirror via smem transpose.
__global__ __launch_bounds__(256, 1) void energy_mma_kernel()
{
    extern __shared__ char smem[];
    const uint32_t sb = smem_to_u32(smem);
    const int b = blockIdx.z;

    // decode triangular (i <= j)
    int t = blockIdx.x, i = 0, rem = 16;
    while (t >= rem) { t -= rem; i++; rem = 16 - i; }
    const int j = i + t;
    const int n0 = i * 128;
    const int m0 = j * 128;

    const __nv_bfloat16* baseH = g_yt_hi + (size_t)b * NN * CC;
    const __nv_bfloat16* baseL = g_yt_lo + (size_t)b * NN * CC;
    float* Sbase = g_s + (size_t)b * NN * NN;

    float acc[4][4][4];
    mma_compute(sb, baseH + (size_t)n0 * CC, baseL + (size_t)n0 * CC, CC,
                baseH + (size_t)m0 * CC, baseL + (size_t)m0 * CC, CC, CC, acc);

    const int lane = threadIdx.x & 31;
    const int wid = threadIdx.x >> 5;
    const int wm = wid >> 2, wn = wid & 3;
    const int r0 = wm * 64 + (lane >> 2);
    const int c0 = wn * 32 + (lane & 3) * 2;

    // direct store
#pragma unroll
    for (int mt = 0; mt < 4; mt++)
#pragma unroll
        for (int nt = 0; nt < 4; nt++) {
            const int row = r0 + mt * 16;
            const int col = c0 + nt * 8;
            *reinterpret_cast<float2*>(Sbase + (size_t)(n0 + row) * NN + m0 + col) =
                make_float2(acc[mt][nt][0], acc[mt][nt][1]);
            *reinterpret_cast<float2*>(Sbase + (size_t)(n0 + row + 8) * NN + m0 + col) =
                make_float2(acc[mt][nt][2], acc[mt][nt][3]);
        }

    if (i == j) return;

    // mirror: stage tile in smem (stride 129 floats), write transposed coalesced
    __syncthreads();
    float* sm = reinterpret_cast<float*>(smem);
#pragma unroll
    for (int mt = 0; mt < 4; mt++)
#pragma unroll
        for (int nt = 0; nt < 4; nt++) {
            const int row = r0 + mt * 16;
            const int col = c0 + nt * 8;
            sm[row * 129 + col] = acc[mt][nt][0];
            sm[row * 129 + col + 1] = acc[mt][nt][1];
            sm[(row + 8) * 129 + col] = acc[mt][nt][2];
            sm[(row + 8) * 129 + col + 1] = acc[mt][nt][3];
        }
    __syncthreads();

    // warp w writes mirror rows p = w*16 .. w*16+15; lane covers 4 cols (q)
#pragma unroll
    for (int iRow = 0; iRow < 16; iRow++) {
        const int p = wid * 16 + iRow;        // local m index = mirror row
        const int q = lane * 4;               // local n index
        float4 v;
        v.x = sm[(q + 0) * 129 + p];
        v.y = sm[(q + 1) * 129 + p];
        v.z = sm[(q + 2) * 129 + p];
        v.w = sm[(q + 3) * 129 + p];
        *reinterpret_cast<float4*>(Sbase + (size_t)(m0 + p) * NN + n0 + q) = v;
    }
}

// projection y^T: D[n][o] = sum_c xt[n][c]*Wqk[o][c], bf16-split epilogue.
__global__ __launch_bounds__(256, 1) void proj_y_mma_kernel()
{
    extern __shared__ char smem[];
    const uint32_t sb = smem_to_u32(smem);
    const int b = blockIdx.z;
    const int o0 = blockIdx.x * 128;
    const int n0 = blockIdx.y * 128;

    const __nv_bfloat16* xtH = g_xt_hi + (size_t)b * NN * CC + (size_t)n0 * CC;
    const __nv_bfloat16* xtL = g_xt_lo + (size_t)b * NN * CC + (size_t)n0 * CC;

    float acc[4][4][4];
    mma_compute(sb, xtH, xtL, CC,
                g_wqk_hi + (size_t)o0 * CC, g_wqk_lo + (size_t)o0 * CC, CC, CC, acc);

    const int lane = threadIdx.x & 31;
    const int wid = threadIdx.x >> 5;
    const int wm = wid >> 2, wn = wid & 3;
    const int r0 = wm * 64 + (lane >> 2);
    const int c0 = wn * 32 + (lane & 3) * 2;

    __nv_bfloat16* Hi = g_yt_hi + (size_t)b * NN * CC + (size_t)n0 * CC + o0;
    __nv_bfloat16* Lo = g_yt_lo + (size_t)b * NN * CC + (size_t)n0 * CC + o0;
#pragma unroll
    for (int mt = 0; mt < 4; mt++)
#pragma unroll
        for (int nt = 0; nt < 4; nt++) {
            const int row = r0 + mt * 16;
            const int col = c0 + nt * 8;
#pragma unroll
            for (int h = 0; h < 2; h++) {
                const int rr = row + h * 8;
                __nv_bfloat16 h0, l0, h1, l1;
                split_bf16(acc[mt][nt][2 * h + 0], h0, l0);
                split_bf16(acc[mt][nt][2 * h + 1], h1, l1);
                __nv_bfloat162 hp; hp.x = h0; hp.y = h1;
                __nv_bfloat162 lp; lp.x = l0; lp.y = l1;
                *reinterpret_cast<__nv_bfloat162*>(Hi + (size_t)rr * CC + col) = hp;
                *reinterpret_cast<__nv_bfloat162*>(Lo + (size_t)rr * CC + col) = lp;
            }
        }
}

// projection v: D[c][n] = sum_k Wv[c][k]*xt[n][k] + bv[c], bf16-split epilogue.
__global__ __launch_bounds__(256, 1) void proj_v_mma_kernel(const float* __restrict__ bv)
{
    extern __shared__ char smem[];
    const uint32_t sb = smem_to_u32(smem);
    const int b = blockIdx.z;
    const int n0 = blockIdx.x * 128;
    const int c0 = blockIdx.y * 128;

    const __nv_bfloat16* xtH = g_xt_hi + (size_t)b * NN * CC + (size_t)n0 * CC;
    const __nv_bfloat16* xtL = g_xt_lo + (size_t)b * NN * CC + (size_t)n0 * CC;

    float acc[4][4][4];
    mma_compute(sb, g_wv_hi + (size_t)c0 * CC, g_wv_lo + (size_t)c0 * CC, CC,
                xtH, xtL, CC, CC, acc);

    const int lane = threadIdx.x & 31;
    const int wid = threadIdx.x >> 5;
    const int wm = wid >> 2, wn = wid & 3;
    const int r0 = wm * 64 + (lane >> 2);
    const int c0l = wn * 32 + (lane & 3) * 2;

    __nv_bfloat16* Hi = g_v_hi + (size_t)b * CC * NN + (size_t)c0 * NN + n0;
    __nv_bfloat16* Lo = g_v_lo + (size_t)b * CC * NN + (size_t)c0 * NN + n0;
    const float* bias = bv + c0;
#pragma unroll
    for (int mt = 0; mt < 4; mt++)
#pragma unroll
        for (int nt = 0; nt < 4; nt++) {
            const int row = r0 + mt * 16;
            const int col = c0l + nt * 8;
#pragma unroll
            for (int h = 0; h < 2; h++) {
                const int rr = row + h * 8;
                const float badd = bias[rr];
                __nv_bfloat16 h0, l0, h1, l1;
                split_bf16(acc[mt][nt][2 * h + 0] + badd, h0, l0);
                split_bf16(acc[mt][nt][2 * h + 1] + badd, h1, l1);
                __nv_bfloat162 hp; hp.x = h0; hp.y = h1;
                __nv_bfloat162 lp; lp.x = l0; lp.y = l1;
                *reinterpret_cast<__nv_bfloat162*>(Hi + (size_t)rr * NN + col) = hp;
                *reinterpret_cast<__nv_bfloat162*>(Lo + (size_t)rr * NN + col) = lp;
            }
        }
}

// out[c][m] = (sum_n v[c][n]*at[m][n]) * rscale[m]
__global__ __launch_bounds__(256, 1) void out_mma_kernel(float* __restrict__ out)
{
    extern __shared__ char smem[];
    const uint32_t sb = smem_to_u32(smem);
    const int b = blockIdx.z;
    const int m0 = blockIdx.x * 128;
    const int c0 = blockIdx.y * 128;
    const __nv_bfloat16* vH = g_v_hi + (size_t)b * CC * NN + (size_t)c0 * NN;
    const __nv_bfloat16* vL = g_v_lo + (size_t)b * CC * NN + (size_t)c0 * NN;
    const __nv_bfloat16* aH = g_at_hi + (size_t)b * NN * NN + (size_t)m0 * NN;
    const __nv_bfloat16* aL = g_at_lo + (size_t)b * NN * NN + (size_t)m0 * NN;

    float acc[4][4][4];
    mma_compute(sb, vH, vL, NN, aH, aL, NN, NN, acc);

    const int lane = threadIdx.x & 31;
    const int wid = threadIdx.x >> 5;
    const int wm = wid >> 2, wn = wid & 3;
    const int r0 = wm * 64 + (lane >> 2);
    const int c0l = wn * 32 + (lane & 3) * 2;
    const float* colscale = g_rscale + (size_t)b * NN + m0;
    float* D = out + (size_t)b * CC * NN + (size_t)c0 * NN + m0;
#pragma unroll
    for (int mt = 0; mt < 4; mt++)
#pragma unroll
        for (int nt = 0; nt < 4; nt++) {
            const int row = r0 + mt * 16;
            const int col = c0l + nt * 8;
            const float s0 = colscale[col], s1 = colscale[col + 1];
            *reinterpret_cast<float2*>(D + (size_t)row * NN + col) =
                make_float2(acc[mt][nt][0] * s0, acc[mt][nt][1] * s1);
            *reinterpret_cast<float2*>(D + (size_t)(row + 8) * NN + col) =
                make_float2(acc[mt][nt][2] * s0, acc[mt][nt][3] * s1);
        }
}

// ---------------------------------------------------------------------------
// Elementwise kernels
// ---------------------------------------------------------------------------

// split W (both) into bf16 hi/lo. grid (CC, 2), 256 threads.
__global__ __launch_bounds__(256) void split_w_kernel(
    const float* __restrict__ Wqk, const float* __restrict__ Wv)
{
    const int o = blockIdx.x;
    const int c = threadIdx.x;
    const int idx = o * CC + c;
    if (blockIdx.y == 0) {
        split_bf16(Wqk[idx], g_wqk_hi[idx], g_wqk_lo[idx]);
    } else {
        split_bf16(Wv[idx], g_wv_hi[idx], g_wv_lo[idx]);
    }
}

// transpose + split x: xt[n][c] = x[c][n]. 64x64 tiles.
__global__ __launch_bounds__(256) void split_x_kernel(const float* __restrict__ x)
{
    __shared__ float t[64][65];
    const int b = blockIdx.z;
    const int c0 = blockIdx.x * 64;   // channel tile
    const int n0 = blockIdx.y * 64;   // position tile
    const float* X = x + (size_t)b * CC * NN;

    const int r = threadIdx.x >> 4;
    const int c4 = (threadIdx.x & 15) * 4;

#pragma unroll
    for (int rr = 0; rr < 4; rr++) {
        const int row = r + rr * 16;   // c - c0
        float4 v = *reinterpret_cast<const float4*>(X + (size_t)(c0 + row) * NN + n0 + c4);
        t[row][c4 + 0] = v.x;
        t[row][c4 + 1] = v.y;
        t[row][c4 + 2] = v.z;
        t[row][c4 + 3] = v.w;
    }
    __syncthreads();

    const size_t ob = (size_t)b * NN * CC;
#pragma unroll
    for (int rr = 0; rr < 4; rr++) {
        const int row = r + rr * 16;   // n - n0
        __align__(8) __nv_bfloat16 hi4[4], lo4[4];
#pragma unroll
        for (int q = 0; q < 4; q++) split_bf16(t[c4 + q][row], hi4[q], lo4[q]);
        const size_t off = ob + (size_t)(n0 + row) * CC + c0 + c4;
        *reinterpret_cast<uint2*>(g_xt_hi + off) = *reinterpret_cast<uint2*>(hi4);
        *reinterpret_cast<uint2*>(g_xt_lo + off) = *reinterpret_cast<uint2*>(lo4);
    }
}

// row softmax over S (in place). One block per row.
__global__ __launch_bounds__(256) void softmax_kernel()
{
    const int tid = threadIdx.x;
    float* __restrict__ row = g_s + ((size_t)blockIdx.y * NN + blockIdx.x) * NN;

    __shared__ float red[8];

    float v[8];
    float mx = -1e30f;
#pragma unroll
    for (int i = 0; i < 8; i++) {
        v[i] = row[i * 256 + tid];
        mx = fmaxf(mx, v[i]);
    }
#pragma unroll
    for (int o = 16; o; o >>= 1) mx = fmaxf(mx, __shfl_xor_sync(0xffffffffu, mx, o));
    if ((tid & 31) == 0) red[tid >> 5] = mx;
    __syncthreads();
    mx = red[0];
#pragma unroll
    for (int i = 1; i < 8; i++) mx = fmaxf(mx, red[i]);
    __syncthreads();

    float s = 0.f;
#pragma unroll
    for (int i = 0; i < 8; i++) {
        v[i] = __expf(v[i] - mx);
        s += v[i];
    }
#pragma unroll
    for (int o = 16; o; o >>= 1) s += __shfl_xor_sync(0xffffffffu, s, o);
    if ((tid & 31) == 0) red[tid >> 5] = s;
    __syncthreads();
    s = red[0];
#pragma unroll
    for (int i = 1; i < 8; i++) s += red[i];

    const float inv = 1.f / s;
#pragma unroll
    for (int i = 0; i < 8; i++) row[i * 256 + tid] = v[i] * inv;
}

// transpose + bf16 split: at[m][n] = softmax(S)[n][m]
__global__ __launch_bounds__(256) void transpose_split_kernel()
{
    __shared__ float t[64][65];
    const int b = blockIdx.z;
    const int m0 = blockIdx.x * 64;
    const int n0 = blockIdx.y * 64;
    const float* S = g_s + (size_t)b * NN * NN;

    const int r = threadIdx.x >> 4;
    const int c4 = (threadIdx.x & 15) * 4;

#pragma unroll
    for (int rr = 0; rr < 4; rr++) {
        const int row = r + rr * 16;
        float4 v = *reinterpret_cast<const float4*>(S + (size_t)(n0 + row) * NN + m0 + c4);
        t[row][c4 + 0] = v.x;
        t[row][c4 + 1] = v.y;
        t[row][c4 + 2] = v.z;
        t[row][c4 + 3] = v.w;
    }
    __syncthreads();

    const size_t ob = (size_t)b * NN * NN;
#pragma unroll
    for (int rr = 0; rr < 4; rr++) {
        const int row = r + rr * 16;   // m - m0
        __align__(8) __nv_bfloat16 hi4[4], lo4[4];
#pragma unroll
        for (int q = 0; q < 4; q++) split_bf16(t[c4 + q][row], hi4[q], lo4[q]);
        const size_t off = ob + (size_t)(m0 + row) * NN + n0 + c4;
        *reinterpret_cast<uint2*>(g_at_hi + off) = *reinterpret_cast<uint2*>(hi4);
        *reinterpret_cast<uint2*>(g_at_lo + off) = *reinterpret_cast<uint2*>(lo4);
    }
}

// colsum over n (rows of at) -> rscale
__global__ __launch_bounds__(256) void colsum_kernel()
{
    const int b = blockIdx.y;
    const int m = blockIdx.x;
    const int tid = threadIdx.x;
    const __nv_bfloat16* rowH = g_at_hi + (size_t)b * NN * NN + (size_t)m * NN;
    const __nv_bfloat16* rowL = g_at_lo + (size_t)b * NN * NN + (size_t)m * NN;

    __shared__ float red[8];

    float s = 0.f;
    {
        uint4 u = *reinterpret_cast<const uint4*>(rowH + tid * 8);
        const __nv_bfloat162* p = reinterpret_cast<const __nv_bfloat162*>(&u);
#pragma unroll
        for (int q = 0; q < 4; q++) {
            float2 f = __bfloat1622float2(p[q]);
            s += f.x + f.y;
        }
        uint4 ul = *reinterpret_cast<const uint4*>(rowL + tid * 8);
        const __nv_bfloat162* pl = reinterpret_cast<const __nv_bfloat162*>(&ul);
#pragma unroll
        for (int q = 0; q < 4; q++) {
            float2 f = __bfloat1622float2(pl[q]);
            s += f.x + f.y;
        }
    }
#pragma unroll
    for (int o = 16; o; o >>= 1) s += __shfl_xor_sync(0xffffffffu, s, o);
    if ((tid & 31) == 0) red[tid >> 5] = s;
    __syncthreads();
    if (tid == 0) {
        float tot = 0.f;
#pragma unroll
        for (int i = 0; i < 8; i++) tot += red[i];
        g_rscale[b * NN + m] = 1.0f / ((1e-9f + tot) * 16.0f);
    }
}

// ---------------------------------------------------------------------------
extern "C" void kernel_launch(void* const* d_in, const int* in_sizes, int n_in,
                              void* d_out, int out_size)
{
    const float* x   = (const float*)d_in[0];
    const float* Wqk = (const float*)d_in[1];
    const float* Wv  = (const float*)d_in[2];
    const float* bv  = (const float*)d_in[3];
    float* out = (float*)d_out;

    cudaFuncSetAttribute(energy_mma_kernel, cudaFuncAttributeMaxDynamicSharedMemorySize, SMEM_MMA);
    cudaFuncSetAttribute(out_mma_kernel, cudaFuncAttributeMaxDynamicSharedMemorySize, SMEM_MMA);
    cudaFuncSetAttribute(proj_y_mma_kernel, cudaFuncAttributeMaxDynamicSharedMemorySize, SMEM_MMA);
    cudaFuncSetAttribute(proj_v_mma_kernel, cudaFuncAttributeMaxDynamicSharedMemorySize, SMEM_MMA);

    split_w_kernel<<<dim3(CC, 2), 256>>>(Wqk, Wv);
    split_x_kernel<<<dim3(CC / 64, NN / 64, BB), 256>>>(x);

    proj_y_mma_kernel<<<dim3(CC / 128, NN / 128, BB), 256, SMEM_MMA>>>();
    proj_v_mma_kernel<<<dim3(NN / 128, CC / 128, BB), 256, SMEM_MMA>>>(bv);

    energy_mma_kernel<<<dim3(136, 1, BB), 256, SMEM_MMA>>>();

    softmax_kernel<<<dim3(NN, BB), 256>>>();

    transpose_split_kernel<<<dim3(NN / 64, NN / 64, BB), 256>>>();

    colsum_kernel<<<dim3(NN, BB), 256>>>();

    out_mma_kernel<<<dim3(NN / 128, CC / 128, BB), 256, SMEM_MMA>>>(out);
}

// round 5
// speedup vs baseline: 2.4839x; 1.1463x over previous
#include <cuda_runtime.h>
#include <cuda_bf16.h>
#include <cstdint>

#define BB 16
#define CC 256
#define NN 2048

// ---------------------------------------------------------------------------
// Scratch (__device__ globals; no allocation allowed)
// ---------------------------------------------------------------------------
__device__ __nv_bfloat16 g_xt_hi[(size_t)BB * NN * CC];  // x^T [b][n][c]
__device__ __nv_bfloat16 g_xt_lo[(size_t)BB * NN * CC];
__device__ __nv_bfloat16 g_wqk_hi[CC * CC];
__device__ __nv_bfloat16 g_wqk_lo[CC * CC];
__device__ __nv_bfloat16 g_wv_hi[CC * CC];
__device__ __nv_bfloat16 g_wv_lo[CC * CC];
__device__ __nv_bfloat16 g_yt_hi[(size_t)BB * NN * CC];  // y^T [b][n][o]
__device__ __nv_bfloat16 g_yt_lo[(size_t)BB * NN * CC];
__device__ __nv_bfloat16 g_v_hi[(size_t)BB * CC * NN];   // v   [b][c][n]
__device__ __nv_bfloat16 g_v_lo[(size_t)BB * CC * NN];
__device__ __nv_bfloat16 g_at_hi[(size_t)BB * NN * NN];  // attention^T [b][m][n]
__device__ __nv_bfloat16 g_at_lo[(size_t)BB * NN * NN];
__device__ float g_s[(size_t)BB * NN * NN];              // energy -> softmax (in place)
__device__ float g_colsum[BB * NN];                      // sum over n of attention[n][m]
__device__ float g_rscale[BB * NN];                      // 1/((1e-9+colsum)*16)

// ---------------------------------------------------------------------------
// Baseline-PTX helpers (no 'a' features)
// ---------------------------------------------------------------------------
__device__ __forceinline__ uint32_t smem_to_u32(const void* smem_ptr) {
    uint32_t addr;
    asm("{ .reg .u64 tmp; cvta.to.shared.u64 tmp, %1; cvt.u32.u64 %0, tmp; }"
        : "=r"(addr) : "l"(smem_ptr));
    return addr;
}

__device__ __forceinline__ void ldsm_x4(uint32_t* r, uint32_t addr) {
    asm volatile("ldmatrix.sync.aligned.m8n8.x4.shared.b16 {%0,%1,%2,%3}, [%4];"
                 : "=r"(r[0]), "=r"(r[1]), "=r"(r[2]), "=r"(r[3]) : "r"(addr));
}

__device__ __forceinline__ void mma_bf16(float* d, const uint32_t* a, const uint32_t* b) {
    asm volatile(
        "mma.sync.aligned.m16n8k16.row.col.f32.bf16.bf16.f32 "
        "{%0,%1,%2,%3},{%4,%5,%6,%7},{%8,%9},{%0,%1,%2,%3};"
        : "+f"(d[0]), "+f"(d[1]), "+f"(d[2]), "+f"(d[3])
        : "r"(a[0]), "r"(a[1]), "r"(a[2]), "r"(a[3]), "r"(b[0]), "r"(b[1]));
}

__device__ __forceinline__ void cp16(uint32_t saddr, const void* g) {
    asm volatile("cp.async.cg.shared.global [%0], [%1], 16;" :: "r"(saddr), "l"(g));
}
__device__ __forceinline__ void cp_commit() {
    asm volatile("cp.async.commit_group;" ::: "memory");
}
template <int N> __device__ __forceinline__ void cp_wait() {
    asm volatile("cp.async.wait_group %0;" :: "n"(N) : "memory");
}

__device__ __forceinline__ void split_bf16(float f, __nv_bfloat16& h, __nv_bfloat16& l) {
    h = __float2bfloat16(f);
    l = __float2bfloat16(f - __bfloat162float(h));
}

// ---------------------------------------------------------------------------
// Warp-MMA GEMM core: acc[128,128] = sum_k (Ah+Al)[r][k]*(Bh+Bl)[c][k]
// NT layout, 256 thr, warp tile 64x32 (2x4 warps), K staged 32, 2-stage
// cp.async pipeline, split-3: AhBh + AhBl + AlBh. Register-lean: A regs are
// reused for the lo pass so the kernel fits 128 regs (2 CTAs/SM).
// ---------------------------------------------------------------------------
#define TSTRIDE 80
#define TILE_BYTES (128 * TSTRIDE)
#define STAGE_BYTES (4 * TILE_BYTES)
#define SMEM_MMA (2 * STAGE_BYTES)      // 81920

__device__ __forceinline__ void fill_stage(
    uint32_t sb, int stage, int k0,
    const __nv_bfloat16* __restrict__ Ah, const __nv_bfloat16* __restrict__ Al, int sA,
    const __nv_bfloat16* __restrict__ Bh, const __nv_bfloat16* __restrict__ Bl, int sB)
{
    const int tid = threadIdx.x;
    const int row = tid >> 1;
    const int half = tid & 1;
    const uint32_t s0 = sb + stage * STAGE_BYTES + row * TSTRIDE + half * 32;
    const int go = k0 + half * 16;
    const __nv_bfloat16* pAh = Ah + (size_t)row * sA + go;
    const __nv_bfloat16* pAl = Al + (size_t)row * sA + go;
    const __nv_bfloat16* pBh = Bh + (size_t)row * sB + go;
    const __nv_bfloat16* pBl = Bl + (size_t)row * sB + go;
    cp16(s0 + 0 * TILE_BYTES, pAh);      cp16(s0 + 0 * TILE_BYTES + 16, pAh + 8);
    cp16(s0 + 1 * TILE_BYTES, pAl);      cp16(s0 + 1 * TILE_BYTES + 16, pAl + 8);
    cp16(s0 + 2 * TILE_BYTES, pBh);      cp16(s0 + 2 * TILE_BYTES + 16, pBh + 8);
    cp16(s0 + 3 * TILE_BYTES, pBl);      cp16(s0 + 3 * TILE_BYTES + 16, pBl + 8);
}

__device__ __forceinline__ void compute_stage(uint32_t sb, int stage, float acc[4][4][4])
{
    const int lane = threadIdx.x & 31;
    const int wid = threadIdx.x >> 5;
    const int wm = wid >> 2;
    const int wn = wid & 3;
    const uint32_t st = sb + stage * STAGE_BYTES;
    const uint32_t laneoff =
        (uint32_t)(((lane & 7) + ((lane >> 3) & 1) * 8) * TSTRIDE + (lane >> 4) * 16);

#pragma unroll
    for (int k16 = 0; k16 < 2; k16++) {
        const uint32_t kb = (uint32_t)(k16 * 32);
        uint32_t b_hi[4][2], b_lo[4][2];
#pragma unroll
        for (int np = 0; np < 2; np++) {
            uint32_t bd = st + 2 * TILE_BYTES +
                          (uint32_t)((wn * 32 + np * 16) * TSTRIDE) + kb + laneoff;
            uint32_t r[4], rl[4];
            ldsm_x4(r, bd);
            ldsm_x4(rl, bd + TILE_BYTES);
            b_hi[np * 2 + 0][0] = r[0];  b_hi[np * 2 + 0][1] = r[2];
            b_hi[np * 2 + 1][0] = r[1];  b_hi[np * 2 + 1][1] = r[3];
            b_lo[np * 2 + 0][0] = rl[0]; b_lo[np * 2 + 0][1] = rl[2];
            b_lo[np * 2 + 1][0] = rl[1]; b_lo[np * 2 + 1][1] = rl[3];
        }
        uint32_t a[4][4];
        // pass 1: A-hi x (B-hi + B-lo)
#pragma unroll
        for (int mt = 0; mt < 4; mt++) {
            uint32_t ad = st + (uint32_t)((wm * 64 + mt * 16) * TSTRIDE) + kb + laneoff;
            ldsm_x4(a[mt], ad);
        }
#pragma unroll
        for (int mt = 0; mt < 4; mt++)
#pragma unroll
            for (int nt = 0; nt < 4; nt++) {
                mma_bf16(acc[mt][nt], a[mt], b_hi[nt]);
                mma_bf16(acc[mt][nt], a[mt], b_lo[nt]);
            }
        // pass 2: A-lo x B-hi (reuse A registers)
#pragma unroll
        for (int mt = 0; mt < 4; mt++) {
            uint32_t ad = st + (uint32_t)((wm * 64 + mt * 16) * TSTRIDE) + kb + laneoff;
            ldsm_x4(a[mt], ad + TILE_BYTES);
        }
#pragma unroll
        for (int mt = 0; mt < 4; mt++)
#pragma unroll
            for (int nt = 0; nt < 4; nt++)
                mma_bf16(acc[mt][nt], a[mt], b_hi[nt]);
    }
}

__device__ __forceinline__ void mma_compute(
    uint32_t sb,
    const __nv_bfloat16* Ah, const __nv_bfloat16* Al, int sA,
    const __nv_bfloat16* Bh, const __nv_bfloat16* Bl, int sB,
    int K, float acc[4][4][4])
{
#pragma unroll
    for (int mt = 0; mt < 4; mt++)
#pragma unroll
        for (int nt = 0; nt < 4; nt++)
#pragma unroll
            for (int q = 0; q < 4; q++) acc[mt][nt][q] = 0.f;

    const int S = K / 32;
    fill_stage(sb, 0, 0, Ah, Al, sA, Bh, Bl, sB);
    cp_commit();

    for (int s = 0; s < S; s++) {
        if (s + 1 < S) {
            fill_stage(sb, (s + 1) & 1, (s + 1) * 32, Ah, Al, sA, Bh, Bl, sB);
            cp_commit();
            cp_wait<1>();
        } else {
            cp_wait<0>();
        }
        __syncthreads();
        compute_stage(sb, s & 1, acc);
        __syncthreads();
    }
}

// ---------------------------------------------------------------------------
// GEMM kernels (all 2-CTA/SM)
// ---------------------------------------------------------------------------

// energy (symmetric): triangular tile enumeration, mirror via smem transpose.
__global__ __launch_bounds__(256, 2) void energy_mma_kernel()
{
    extern __shared__ char smem[];
    const uint32_t sb = smem_to_u32(smem);
    const int b = blockIdx.z;

    int t = blockIdx.x, i = 0, rem = 16;
    while (t >= rem) { t -= rem; i++; rem = 16 - i; }
    const int j = i + t;
    const int n0 = i * 128;
    const int m0 = j * 128;

    const __nv_bfloat16* baseH = g_yt_hi + (size_t)b * NN * CC;
    const __nv_bfloat16* baseL = g_yt_lo + (size_t)b * NN * CC;
    float* Sbase = g_s + (size_t)b * NN * NN;

    float acc[4][4][4];
    mma_compute(sb, baseH + (size_t)n0 * CC, baseL + (size_t)n0 * CC, CC,
                baseH + (size_t)m0 * CC, baseL + (size_t)m0 * CC, CC, CC, acc);

    const int lane = threadIdx.x & 31;
    const int wid = threadIdx.x >> 5;
    const int wm = wid >> 2, wn = wid & 3;
    const int r0 = wm * 64 + (lane >> 2);
    const int c0 = wn * 32 + (lane & 3) * 2;

#pragma unroll
    for (int mt = 0; mt < 4; mt++)
#pragma unroll
        for (int nt = 0; nt < 4; nt++) {
            const int row = r0 + mt * 16;
            const int col = c0 + nt * 8;
            *reinterpret_cast<float2*>(Sbase + (size_t)(n0 + row) * NN + m0 + col) =
                make_float2(acc[mt][nt][0], acc[mt][nt][1]);
            *reinterpret_cast<float2*>(Sbase + (size_t)(n0 + row + 8) * NN + m0 + col) =
                make_float2(acc[mt][nt][2], acc[mt][nt][3]);
        }

    if (i == j) return;

    __syncthreads();
    float* sm = reinterpret_cast<float*>(smem);
#pragma unroll
    for (int mt = 0; mt < 4; mt++)
#pragma unroll
        for (int nt = 0; nt < 4; nt++) {
            const int row = r0 + mt * 16;
            const int col = c0 + nt * 8;
            sm[row * 129 + col] = acc[mt][nt][0];
            sm[row * 129 + col + 1] = acc[mt][nt][1];
            sm[(row + 8) * 129 + col] = acc[mt][nt][2];
            sm[(row + 8) * 129 + col + 1] = acc[mt][nt][3];
        }
    __syncthreads();

#pragma unroll
    for (int iRow = 0; iRow < 16; iRow++) {
        const int p = wid * 16 + iRow;
        const int q = lane * 4;
        float4 v;
        v.x = sm[(q + 0) * 129 + p];
        v.y = sm[(q + 1) * 129 + p];
        v.z = sm[(q + 2) * 129 + p];
        v.w = sm[(q + 3) * 129 + p];
        *reinterpret_cast<float4*>(Sbase + (size_t)(m0 + p) * NN + n0 + q) = v;
    }
}

// projection y^T: D[n][o] = sum_c xt[n][c]*Wqk[o][c], bf16-split epilogue.
__global__ __launch_bounds__(256, 2) void proj_y_mma_kernel()
{
    extern __shared__ char smem[];
    const uint32_t sb = smem_to_u32(smem);
    const int b = blockIdx.z;
    const int o0 = blockIdx.x * 128;
    const int n0 = blockIdx.y * 128;

    const __nv_bfloat16* xtH = g_xt_hi + (size_t)b * NN * CC + (size_t)n0 * CC;
    const __nv_bfloat16* xtL = g_xt_lo + (size_t)b * NN * CC + (size_t)n0 * CC;

    float acc[4][4][4];
    mma_compute(sb, xtH, xtL, CC,
                g_wqk_hi + (size_t)o0 * CC, g_wqk_lo + (size_t)o0 * CC, CC, CC, acc);

    const int lane = threadIdx.x & 31;
    const int wid = threadIdx.x >> 5;
    const int wm = wid >> 2, wn = wid & 3;
    const int r0 = wm * 64 + (lane >> 2);
    const int c0 = wn * 32 + (lane & 3) * 2;

    __nv_bfloat16* Hi = g_yt_hi + (size_t)b * NN * CC + (size_t)n0 * CC + o0;
    __nv_bfloat16* Lo = g_yt_lo + (size_t)b * NN * CC + (size_t)n0 * CC + o0;
#pragma unroll
    for (int mt = 0; mt < 4; mt++)
#pragma unroll
        for (int nt = 0; nt < 4; nt++) {
            const int row = r0 + mt * 16;
            const int col = c0 + nt * 8;
#pragma unroll
            for (int h = 0; h < 2; h++) {
                const int rr = row + h * 8;
                __nv_bfloat16 h0, l0, h1, l1;
                split_bf16(acc[mt][nt][2 * h + 0], h0, l0);
                split_bf16(acc[mt][nt][2 * h + 1], h1, l1);
                __nv_bfloat162 hp; hp.x = h0; hp.y = h1;
                __nv_bfloat162 lp; lp.x = l0; lp.y = l1;
                *reinterpret_cast<__nv_bfloat162*>(Hi + (size_t)rr * CC + col) = hp;
                *reinterpret_cast<__nv_bfloat162*>(Lo + (size_t)rr * CC + col) = lp;
            }
        }
}

// projection v: D[c][n] = sum_k Wv[c][k]*xt[n][k] + bv[c], bf16-split epilogue.
__global__ __launch_bounds__(256, 2) void proj_v_mma_kernel(const float* __restrict__ bv)
{
    extern __shared__ char smem[];
    const uint32_t sb = smem_to_u32(smem);
    const int b = blockIdx.z;
    const int n0 = blockIdx.x * 128;
    const int c0 = blockIdx.y * 128;

    const __nv_bfloat16* xtH = g_xt_hi + (size_t)b * NN * CC + (size_t)n0 * CC;
    const __nv_bfloat16* xtL = g_xt_lo + (size_t)b * NN * CC + (size_t)n0 * CC;

    float acc[4][4][4];
    mma_compute(sb, g_wv_hi + (size_t)c0 * CC, g_wv_lo + (size_t)c0 * CC, CC,
                xtH, xtL, CC, CC, acc);

    const int lane = threadIdx.x & 31;
    const int wid = threadIdx.x >> 5;
    const int wm = wid >> 2, wn = wid & 3;
    const int r0 = wm * 64 + (lane >> 2);
    const int c0l = wn * 32 + (lane & 3) * 2;

    __nv_bfloat16* Hi = g_v_hi + (size_t)b * CC * NN + (size_t)c0 * NN + n0;
    __nv_bfloat16* Lo = g_v_lo + (size_t)b * CC * NN + (size_t)c0 * NN + n0;
    const float* bias = bv + c0;
#pragma unroll
    for (int mt = 0; mt < 4; mt++)
#pragma unroll
        for (int nt = 0; nt < 4; nt++) {
            const int row = r0 + mt * 16;
            const int col = c0l + nt * 8;
#pragma unroll
            for (int h = 0; h < 2; h++) {
                const int rr = row + h * 8;
                const float badd = bias[rr];
                __nv_bfloat16 h0, l0, h1, l1;
                split_bf16(acc[mt][nt][2 * h + 0] + badd, h0, l0);
                split_bf16(acc[mt][nt][2 * h + 1] + badd, h1, l1);
                __nv_bfloat162 hp; hp.x = h0; hp.y = h1;
                __nv_bfloat162 lp; lp.x = l0; lp.y = l1;
                *reinterpret_cast<__nv_bfloat162*>(Hi + (size_t)rr * NN + col) = hp;
                *reinterpret_cast<__nv_bfloat162*>(Lo + (size_t)rr * NN + col) = lp;
            }
        }
}

// out[c][m] = (sum_n v[c][n]*at[m][n]) * rscale[m]
__global__ __launch_bounds__(256, 2) void out_mma_kernel(float* __restrict__ out)
{
    extern __shared__ char smem[];
    const uint32_t sb = smem_to_u32(smem);
    const int b = blockIdx.z;
    const int m0 = blockIdx.x * 128;
    const int c0 = blockIdx.y * 128;
    const __nv_bfloat16* vH = g_v_hi + (size_t)b * CC * NN + (size_t)c0 * NN;
    const __nv_bfloat16* vL = g_v_lo + (size_t)b * CC * NN + (size_t)c0 * NN;
    const __nv_bfloat16* aH = g_at_hi + (size_t)b * NN * NN + (size_t)m0 * NN;
    const __nv_bfloat16* aL = g_at_lo + (size_t)b * NN * NN + (size_t)m0 * NN;

    float acc[4][4][4];
    mma_compute(sb, vH, vL, NN, aH, aL, NN, NN, acc);

    const int lane = threadIdx.x & 31;
    const int wid = threadIdx.x >> 5;
    const int wm = wid >> 2, wn = wid & 3;
    const int r0 = wm * 64 + (lane >> 2);
    const int c0l = wn * 32 + (lane & 3) * 2;
    const float* colscale = g_rscale + (size_t)b * NN + m0;
    float* D = out + (size_t)b * CC * NN + (size_t)c0 * NN + m0;
#pragma unroll
    for (int mt = 0; mt < 4; mt++)
#pragma unroll
        for (int nt = 0; nt < 4; nt++) {
            const int row = r0 + mt * 16;
            const int col = c0l + nt * 8;
            const float s0 = colscale[col], s1 = colscale[col + 1];
            *reinterpret_cast<float2*>(D + (size_t)row * NN + col) =
                make_float2(acc[mt][nt][0] * s0, acc[mt][nt][1] * s1);
            *reinterpret_cast<float2*>(D + (size_t)(row + 8) * NN + col) =
                make_float2(acc[mt][nt][2] * s0, acc[mt][nt][3] * s1);
        }
}

// ---------------------------------------------------------------------------
// Elementwise kernels
// ---------------------------------------------------------------------------

__global__ __launch_bounds__(256) void split_w_kernel(
    const float* __restrict__ Wqk, const float* __restrict__ Wv)
{
    const int o = blockIdx.x;
    const int c = threadIdx.x;
    const int idx = o * CC + c;
    if (blockIdx.y == 0) {
        split_bf16(Wqk[idx], g_wqk_hi[idx], g_wqk_lo[idx]);
    } else {
        split_bf16(Wv[idx], g_wv_hi[idx], g_wv_lo[idx]);
    }
}

// transpose + split x: xt[n][c] = x[c][n]. 64x64 tiles.
__global__ __launch_bounds__(256) void split_x_kernel(const float* __restrict__ x)
{
    __shared__ float t[64][65];
    const int b = blockIdx.z;
    const int c0 = blockIdx.x * 64;
    const int n0 = blockIdx.y * 64;
    const float* X = x + (size_t)b * CC * NN;

    const int r = threadIdx.x >> 4;
    const int c4 = (threadIdx.x & 15) * 4;

#pragma unroll
    for (int rr = 0; rr < 4; rr++) {
        const int row = r + rr * 16;
        float4 v = *reinterpret_cast<const float4*>(X + (size_t)(c0 + row) * NN + n0 + c4);
        t[row][c4 + 0] = v.x;
        t[row][c4 + 1] = v.y;
        t[row][c4 + 2] = v.z;
        t[row][c4 + 3] = v.w;
    }
    __syncthreads();

    const size_t ob = (size_t)b * NN * CC;
#pragma unroll
    for (int rr = 0; rr < 4; rr++) {
        const int row = r + rr * 16;
        __align__(8) __nv_bfloat16 hi4[4], lo4[4];
#pragma unroll
        for (int q = 0; q < 4; q++) split_bf16(t[c4 + q][row], hi4[q], lo4[q]);
        const size_t off = ob + (size_t)(n0 + row) * CC + c0 + c4;
        *reinterpret_cast<uint2*>(g_xt_hi + off) = *reinterpret_cast<uint2*>(hi4);
        *reinterpret_cast<uint2*>(g_xt_lo + off) = *reinterpret_cast<uint2*>(lo4);
    }
}

// row softmax over S (in place). One block per row.
__global__ __launch_bounds__(256) void softmax_kernel()
{
    const int tid = threadIdx.x;
    float* __restrict__ row = g_s + ((size_t)blockIdx.y * NN + blockIdx.x) * NN;

    __shared__ float red[8];

    float v[8];
    float mx = -1e30f;
#pragma unroll
    for (int i = 0; i < 8; i++) {
        v[i] = row[i * 256 + tid];
        mx = fmaxf(mx, v[i]);
    }
#pragma unroll
    for (int o = 16; o; o >>= 1) mx = fmaxf(mx, __shfl_xor_sync(0xffffffffu, mx, o));
    if ((tid & 31) == 0) red[tid >> 5] = mx;
    __syncthreads();
    mx = red[0];
#pragma unroll
    for (int i = 1; i < 8; i++) mx = fmaxf(mx, red[i]);
    __syncthreads();

    float s = 0.f;
#pragma unroll
    for (int i = 0; i < 8; i++) {
        v[i] = __expf(v[i] - mx);
        s += v[i];
    }
#pragma unroll
    for (int o = 16; o; o >>= 1) s += __shfl_xor_sync(0xffffffffu, s, o);
    if ((tid & 31) == 0) red[tid >> 5] = s;
    __syncthreads();
    s = red[0];
#pragma unroll
    for (int i = 1; i < 8; i++) s += red[i];

    const float inv = 1.f / s;
#pragma unroll
    for (int i = 0; i < 8; i++) row[i * 256 + tid] = v[i] * inv;
}

// zero colsums (deterministic per launch)
__global__ __launch_bounds__(256) void zero_colsum_kernel()
{
    g_colsum[blockIdx.x * 256 + threadIdx.x] = 0.f;
}

// transpose + bf16 split: at[m][n] = softmax(S)[n][m]; also accumulates
// column sums (over n) into g_colsum via one atomicAdd per (tile, m).
__global__ __launch_bounds__(256) void transpose_split_kernel()
{
    __shared__ float t[64][65];
    const int b = blockIdx.z;
    const int m0 = blockIdx.x * 64;
    const int n0 = blockIdx.y * 64;
    const float* S = g_s + (size_t)b * NN * NN;

    const int tid = threadIdx.x;
    const int lane = tid & 31;
    const int r = tid >> 4;
    const int c4 = (tid & 15) * 4;

#pragma unroll
    for (int rr = 0; rr < 4; rr++) {
        const int row = r + rr * 16;   // n - n0
        float4 v = *reinterpret_cast<const float4*>(S + (size_t)(n0 + row) * NN + m0 + c4);
        t[row][c4 + 0] = v.x;
        t[row][c4 + 1] = v.y;
        t[row][c4 + 2] = v.z;
        t[row][c4 + 3] = v.w;
    }
    __syncthreads();

    const size_t ob = (size_t)b * NN * NN;
#pragma unroll
    for (int rr = 0; rr < 4; rr++) {
        const int row = r + rr * 16;   // m - m0
        // partial colsum over this thread's 4 n values
        float ps = t[c4 + 0][row] + t[c4 + 1][row] + t[c4 + 2][row] + t[c4 + 3][row];
#pragma unroll
        for (int o = 1; o < 16; o <<= 1) ps += __shfl_xor_sync(0xffffffffu, ps, o);
        if ((lane & 15) == 0) atomicAdd(&g_colsum[b * NN + m0 + row], ps);

        __align__(8) __nv_bfloat16 hi4[4], lo4[4];
#pragma unroll
        for (int q = 0; q < 4; q++) split_bf16(t[c4 + q][row], hi4[q], lo4[q]);
        const size_t off = ob + (size_t)(m0 + row) * NN + n0 + c4;
        *reinterpret_cast<uint2*>(g_at_hi + off) = *reinterpret_cast<uint2*>(hi4);
        *reinterpret_cast<uint2*>(g_at_lo + off) = *reinterpret_cast<uint2*>(lo4);
    }
}

__global__ __launch_bounds__(256) void rscale_kernel()
{
    const int i = blockIdx.x * 256 + threadIdx.x;
    g_rscale[i] = 1.0f / ((1e-9f + g_colsum[i]) * 16.0f);
}

// ---------------------------------------------------------------------------
extern "C" void kernel_launch(void* const* d_in, const int* in_sizes, int n_in,
                              void* d_out, int out_size)
{
    const float* x   = (const float*)d_in[0];
    const float* Wqk = (const float*)d_in[1];
    const float* Wv  = (const float*)d_in[2];
    const float* bv  = (const float*)d_in[3];
    float* out = (float*)d_out;

    cudaFuncSetAttribute(energy_mma_kernel, cudaFuncAttributeMaxDynamicSharedMemorySize, SMEM_MMA);
    cudaFuncSetAttribute(out_mma_kernel, cudaFuncAttributeMaxDynamicSharedMemorySize, SMEM_MMA);
    cudaFuncSetAttribute(proj_y_mma_kernel, cudaFuncAttributeMaxDynamicSharedMemorySize, SMEM_MMA);
    cudaFuncSetAttribute(proj_v_mma_kernel, cudaFuncAttributeMaxDynamicSharedMemorySize, SMEM_MMA);

    split_w_kernel<<<dim3(CC, 2), 256>>>(Wqk, Wv);
    split_x_kernel<<<dim3(CC / 64, NN / 64, BB), 256>>>(x);

    proj_y_mma_kernel<<<dim3(CC / 128, NN / 128, BB), 256, SMEM_MMA>>>();
    proj_v_mma_kernel<<<dim3(NN / 128, CC / 128, BB), 256, SMEM_MMA>>>(bv);

    energy_mma_kernel<<<dim3(136, 1, BB), 256, SMEM_MMA>>>();

    zero_colsum_kernel<<<BB * NN / 256, 256>>>();

    softmax_kernel<<<dim3(NN, BB), 256>>>();

    transpose_split_kernel<<<dim3(NN / 64, NN / 64, BB), 256>>>();

    rscale_kernel<<<BB * NN / 256, 256>>>();

    out_mma_kernel<<<dim3(NN / 128, CC / 128, BB), 256, SMEM_MMA>>>(out);
}

// round 7
// speedup vs baseline: 2.5851x; 1.0407x over previous
#include <cuda_runtime.h>
#include <cuda_bf16.h>
#include <cstdint>

#define BB 16
#define CC 256
#define NN 2048

// ---------------------------------------------------------------------------
// Scratch (__device__ globals; no allocation allowed)
// ---------------------------------------------------------------------------
__device__ __nv_bfloat16 g_xt_hi[(size_t)BB * NN * CC];  // x^T [b][n][c]
__device__ __nv_bfloat16 g_xt_lo[(size_t)BB * NN * CC];
__device__ __nv_bfloat16 g_wqk_hi[CC * CC];
__device__ __nv_bfloat16 g_wqk_lo[CC * CC];
__device__ __nv_bfloat16 g_wv_hi[CC * CC];
__device__ __nv_bfloat16 g_wv_lo[CC * CC];
__device__ __nv_bfloat16 g_yt_hi[(size_t)BB * NN * CC];  // y^T [b][n][o]
__device__ __nv_bfloat16 g_yt_lo[(size_t)BB * NN * CC];
__device__ __nv_bfloat16 g_v_hi[(size_t)BB * CC * NN];   // v   [b][c][n]
__device__ __nv_bfloat16 g_v_lo[(size_t)BB * CC * NN];
__device__ __nv_bfloat16 g_at_hi[(size_t)BB * NN * NN];  // attention^T [b][m][n]
__device__ __nv_bfloat16 g_at_lo[(size_t)BB * NN * NN];
__device__ float g_s[(size_t)BB * NN * NN];              // energy -> softmax (in place)
__device__ float g_colsum[BB * NN];                      // sum over n of attention[n][m]
__device__ float g_rscale[BB * NN];                      // 1/((1e-9+colsum)*16)

// ---------------------------------------------------------------------------
// Baseline-PTX helpers (no 'a' features)
// ---------------------------------------------------------------------------
__device__ __forceinline__ uint32_t smem_to_u32(const void* smem_ptr) {
    uint32_t addr;
    asm("{ .reg .u64 tmp; cvta.to.shared.u64 tmp, %1; cvt.u32.u64 %0, tmp; }"
        : "=r"(addr) : "l"(smem_ptr));
    return addr;
}

__device__ __forceinline__ void ldsm_x4(uint32_t* r, uint32_t addr) {
    asm volatile("ldmatrix.sync.aligned.m8n8.x4.shared.b16 {%0,%1,%2,%3}, [%4];"
                 : "=r"(r[0]), "=r"(r[1]), "=r"(r[2]), "=r"(r[3]) : "r"(addr));
}

__device__ __forceinline__ void mma_bf16(float* d, const uint32_t* a, const uint32_t* b) {
    asm volatile(
        "mma.sync.aligned.m16n8k16.row.col.f32.bf16.bf16.f32 "
        "{%0,%1,%2,%3},{%4,%5,%6,%7},{%8,%9},{%0,%1,%2,%3};"
        : "+f"(d[0]), "+f"(d[1]), "+f"(d[2]), "+f"(d[3])
        : "r"(a[0]), "r"(a[1]), "r"(a[2]), "r"(a[3]), "r"(b[0]), "r"(b[1]));
}

__device__ __forceinline__ void cp16(uint32_t saddr, const void* g) {
    asm volatile("cp.async.cg.shared.global [%0], [%1], 16;" :: "r"(saddr), "l"(g));
}
__device__ __forceinline__ void cp_commit() {
    asm volatile("cp.async.commit_group;" ::: "memory");
}
template <int N> __device__ __forceinline__ void cp_wait() {
    asm volatile("cp.async.wait_group %0;" :: "n"(N) : "memory");
}

__device__ __forceinline__ void split_bf16(float f, __nv_bfloat16& h, __nv_bfloat16& l) {
    h = __float2bfloat16(f);
    l = __float2bfloat16(f - __bfloat162float(h));
}

// ---------------------------------------------------------------------------
// Warp-MMA GEMM core: acc[128,128] = sum_k (Ah+Al)[r][k]*(Bh+Bl)[c][k]
// NT layout, 256 thr, warp tile 64x32 (2x4 warps). 4-stage cp.async pipeline
// with K=16 stages, ONE __syncthreads per stage. Split-3: AhBh + AhBl + AlBh.
// TSTRIDE=48: 16B-aligned rows (cp.async/ldmatrix req), conflict-free banks.
// ---------------------------------------------------------------------------
#define TSTRIDE 48                        // 16 bf16 = 32B payload + 16B pad
#define TILE_BYTES (128 * TSTRIDE)        // 6144
#define STAGE_BYTES (4 * TILE_BYTES)      // 24576: Ah, Al, Bh, Bl
#define NSTAGE 4
#define SMEM_MMA (NSTAGE * STAGE_BYTES)   // 98304

__device__ __forceinline__ void fill_stage(
    uint32_t sb, int stage, int k0,
    const __nv_bfloat16* __restrict__ Ah, const __nv_bfloat16* __restrict__ Al, int sA,
    const __nv_bfloat16* __restrict__ Bh, const __nv_bfloat16* __restrict__ Bl, int sB)
{
    const int tid = threadIdx.x;
    const int row = tid >> 1;             // 0..127
    const int half = tid & 1;             // 0..1 (8 bf16 each)
    const uint32_t s0 = sb + stage * STAGE_BYTES + row * TSTRIDE + half * 16;
    const int go = k0 + half * 8;
    cp16(s0 + 0 * TILE_BYTES, Ah + (size_t)row * sA + go);
    cp16(s0 + 1 * TILE_BYTES, Al + (size_t)row * sA + go);
    cp16(s0 + 2 * TILE_BYTES, Bh + (size_t)row * sB + go);
    cp16(s0 + 3 * TILE_BYTES, Bl + (size_t)row * sB + go);
}

__device__ __forceinline__ void compute_stage(uint32_t sb, int stage, float acc[4][4][4])
{
    const int lane = threadIdx.x & 31;
    const int wid = threadIdx.x >> 5;
    const int wm = wid >> 2;              // 0..1
    const int wn = wid & 3;               // 0..3
    const uint32_t st = sb + stage * STAGE_BYTES;
    // ldmatrix.x4 over a 16x16 bf16 tile: lanes 0-15 -> rows 0-15 (k lo 16B),
    // lanes 16-31 -> rows 0-15 (k hi 16B).
    const uint32_t laneoff = (uint32_t)((lane & 15) * TSTRIDE + (lane >> 4) * 16);

    uint32_t b_hi[4][2], b_lo[4][2];
#pragma unroll
    for (int np = 0; np < 2; np++) {
        uint32_t bd = st + 2 * TILE_BYTES + (uint32_t)((wn * 32 + np * 16) * TSTRIDE) + laneoff;
        uint32_t r[4], rl[4];
        ldsm_x4(r, bd);
        ldsm_x4(rl, bd + TILE_BYTES);
        b_hi[np * 2 + 0][0] = r[0];  b_hi[np * 2 + 0][1] = r[2];
        b_hi[np * 2 + 1][0] = r[1];  b_hi[np * 2 + 1][1] = r[3];
        b_lo[np * 2 + 0][0] = rl[0]; b_lo[np * 2 + 0][1] = rl[2];
        b_lo[np * 2 + 1][0] = rl[1]; b_lo[np * 2 + 1][1] = rl[3];
    }
    uint32_t a[4][4];
    // pass 1: A-hi x (B-hi + B-lo)
#pragma unroll
    for (int mt = 0; mt < 4; mt++) {
        uint32_t ad = st + (uint32_t)((wm * 64 + mt * 16) * TSTRIDE) + laneoff;
        ldsm_x4(a[mt], ad);
    }
#pragma unroll
    for (int mt = 0; mt < 4; mt++)
#pragma unroll
        for (int nt = 0; nt < 4; nt++) {
            mma_bf16(acc[mt][nt], a[mt], b_hi[nt]);
            mma_bf16(acc[mt][nt], a[mt], b_lo[nt]);
        }
    // pass 2: A-lo x B-hi (reuse A registers)
#pragma unroll
    for (int mt = 0; mt < 4; mt++) {
        uint32_t ad = st + (uint32_t)((wm * 64 + mt * 16) * TSTRIDE) + laneoff;
        ldsm_x4(a[mt], ad + TILE_BYTES);
    }
#pragma unroll
    for (int mt = 0; mt < 4; mt++)
#pragma unroll
        for (int nt = 0; nt < 4; nt++)
            mma_bf16(acc[mt][nt], a[mt], b_hi[nt]);
}

__device__ __forceinline__ void mma_compute(
    uint32_t sb,
    const __nv_bfloat16* Ah, const __nv_bfloat16* Al, int sA,
    const __nv_bfloat16* Bh, const __nv_bfloat16* Bl, int sB,
    int K, float acc[4][4][4])
{
#pragma unroll
    for (int mt = 0; mt < 4; mt++)
#pragma unroll
        for (int nt = 0; nt < 4; nt++)
#pragma unroll
            for (int q = 0; q < 4; q++) acc[mt][nt][q] = 0.f;

    const int S = K / 16;   // K >= 256 always, so S >= 16 > NSTAGE
    // prologue: fill NSTAGE-1 stages
#pragma unroll
    for (int p = 0; p < NSTAGE - 1; p++) {
        fill_stage(sb, p, p * 16, Ah, Al, sA, Bh, Bl, sB);
        cp_commit();
    }

    for (int s = 0; s < S; s++) {
        cp_wait<NSTAGE - 2>();
        __syncthreads();
        compute_stage(sb, s & (NSTAGE - 1), acc);
        const int f = s + NSTAGE - 1;
        if (f < S)
            fill_stage(sb, f & (NSTAGE - 1), f * 16, Ah, Al, sA, Bh, Bl, sB);
        cp_commit();
    }
}

// ---------------------------------------------------------------------------
// GEMM kernels (all 2-CTA/SM)
// ---------------------------------------------------------------------------

// energy (symmetric): triangular tile enumeration, mirror via smem transpose.
__global__ __launch_bounds__(256, 2) void energy_mma_kernel()
{
    extern __shared__ char smem[];
    const uint32_t sb = smem_to_u32(smem);
    const int b = blockIdx.z;

    int t = blockIdx.x, i = 0, rem = 16;
    while (t >= rem) { t -= rem; i++; rem = 16 - i; }
    const int j = i + t;
    const int n0 = i * 128;
    const int m0 = j * 128;

    const __nv_bfloat16* baseH = g_yt_hi + (size_t)b * NN * CC;
    const __nv_bfloat16* baseL = g_yt_lo + (size_t)b * NN * CC;
    float* Sbase = g_s + (size_t)b * NN * NN;

    float acc[4][4][4];
    mma_compute(sb, baseH + (size_t)n0 * CC, baseL + (size_t)n0 * CC, CC,
                baseH + (size_t)m0 * CC, baseL + (size_t)m0 * CC, CC, CC, acc);

    const int lane = threadIdx.x & 31;
    const int wid = threadIdx.x >> 5;
    const int wm = wid >> 2, wn = wid & 3;
    const int r0 = wm * 64 + (lane >> 2);
    const int c0 = wn * 32 + (lane & 3) * 2;

#pragma unroll
    for (int mt = 0; mt < 4; mt++)
#pragma unroll
        for (int nt = 0; nt < 4; nt++) {
            const int row = r0 + mt * 16;
            const int col = c0 + nt * 8;
            *reinterpret_cast<float2*>(Sbase + (size_t)(n0 + row) * NN + m0 + col) =
                make_float2(acc[mt][nt][0], acc[mt][nt][1]);
            *reinterpret_cast<float2*>(Sbase + (size_t)(n0 + row + 8) * NN + m0 + col) =
                make_float2(acc[mt][nt][2], acc[mt][nt][3]);
        }

    if (i == j) return;

    __syncthreads();
    float* sm = reinterpret_cast<float*>(smem);
#pragma unroll
    for (int mt = 0; mt < 4; mt++)
#pragma unroll
        for (int nt = 0; nt < 4; nt++) {
            const int row = r0 + mt * 16;
            const int col = c0 + nt * 8;
            sm[row * 129 + col] = acc[mt][nt][0];
            sm[row * 129 + col + 1] = acc[mt][nt][1];
            sm[(row + 8) * 129 + col] = acc[mt][nt][2];
            sm[(row + 8) * 129 + col + 1] = acc[mt][nt][3];
        }
    __syncthreads();

#pragma unroll
    for (int iRow = 0; iRow < 16; iRow++) {
        const int p = wid * 16 + iRow;
        const int q = lane * 4;
        float4 v;
        v.x = sm[(q + 0) * 129 + p];
        v.y = sm[(q + 1) * 129 + p];
        v.z = sm[(q + 2) * 129 + p];
        v.w = sm[(q + 3) * 129 + p];
        *reinterpret_cast<float4*>(Sbase + (size_t)(m0 + p) * NN + n0 + q) = v;
    }
}

// projection y^T: D[n][o] = sum_c xt[n][c]*Wqk[o][c], bf16-split epilogue.
__global__ __launch_bounds__(256, 2) void proj_y_mma_kernel()
{
    extern __shared__ char smem[];
    const uint32_t sb = smem_to_u32(smem);
    const int b = blockIdx.z;
    const int o0 = blockIdx.x * 128;
    const int n0 = blockIdx.y * 128;

    const __nv_bfloat16* xtH = g_xt_hi + (size_t)b * NN * CC + (size_t)n0 * CC;
    const __nv_bfloat16* xtL = g_xt_lo + (size_t)b * NN * CC + (size_t)n0 * CC;

    float acc[4][4][4];
    mma_compute(sb, xtH, xtL, CC,
                g_wqk_hi + (size_t)o0 * CC, g_wqk_lo + (size_t)o0 * CC, CC, CC, acc);

    const int lane = threadIdx.x & 31;
    const int wid = threadIdx.x >> 5;
    const int wm = wid >> 2, wn = wid & 3;
    const int r0 = wm * 64 + (lane >> 2);
    const int c0 = wn * 32 + (lane & 3) * 2;

    __nv_bfloat16* Hi = g_yt_hi + (size_t)b * NN * CC + (size_t)n0 * CC + o0;
    __nv_bfloat16* Lo = g_yt_lo + (size_t)b * NN * CC + (size_t)n0 * CC + o0;
#pragma unroll
    for (int mt = 0; mt < 4; mt++)
#pragma unroll
        for (int nt = 0; nt < 4; nt++) {
            const int row = r0 + mt * 16;
            const int col = c0 + nt * 8;
#pragma unroll
            for (int h = 0; h < 2; h++) {
                const int rr = row + h * 8;
                __nv_bfloat16 h0, l0, h1, l1;
                split_bf16(acc[mt][nt][2 * h + 0], h0, l0);
                split_bf16(acc[mt][nt][2 * h + 1], h1, l1);
                __nv_bfloat162 hp; hp.x = h0; hp.y = h1;
                __nv_bfloat162 lp; lp.x = l0; lp.y = l1;
                *reinterpret_cast<__nv_bfloat162*>(Hi + (size_t)rr * CC + col) = hp;
                *reinterpret_cast<__nv_bfloat162*>(Lo + (size_t)rr * CC + col) = lp;
            }
        }
}

// projection v: D[c][n] = sum_k Wv[c][k]*xt[n][k] + bv[c], bf16-split epilogue.
__global__ __launch_bounds__(256, 2) void proj_v_mma_kernel(const float* __restrict__ bv)
{
    extern __shared__ char smem[];
    const uint32_t sb = smem_to_u32(smem);
    const int b = blockIdx.z;
    const int n0 = blockIdx.x * 128;
    const int c0 = blockIdx.y * 128;

    const __nv_bfloat16* xtH = g_xt_hi + (size_t)b * NN * CC + (size_t)n0 * CC;
    const __nv_bfloat16* xtL = g_xt_lo + (size_t)b * NN * CC + (size_t)n0 * CC;

    float acc[4][4][4];
    mma_compute(sb, g_wv_hi + (size_t)c0 * CC, g_wv_lo + (size_t)c0 * CC, CC,
                xtH, xtL, CC, CC, acc);

    const int lane = threadIdx.x & 31;
    const int wid = threadIdx.x >> 5;
    const int wm = wid >> 2, wn = wid & 3;
    const int r0 = wm * 64 + (lane >> 2);
    const int c0l = wn * 32 + (lane & 3) * 2;

    __nv_bfloat16* Hi = g_v_hi + (size_t)b * CC * NN + (size_t)c0 * NN + n0;
    __nv_bfloat16* Lo = g_v_lo + (size_t)b * CC * NN + (size_t)c0 * NN + n0;
    const float* bias = bv + c0;
#pragma unroll
    for (int mt = 0; mt < 4; mt++)
#pragma unroll
        for (int nt = 0; nt < 4; nt++) {
            const int row = r0 + mt * 16;
            const int col = c0l + nt * 8;
#pragma unroll
            for (int h = 0; h < 2; h++) {
                const int rr = row + h * 8;
                const float badd = bias[rr];
                __nv_bfloat16 h0, l0, h1, l1;
                split_bf16(acc[mt][nt][2 * h + 0] + badd, h0, l0);
                split_bf16(acc[mt][nt][2 * h + 1] + badd, h1, l1);
                __nv_bfloat162 hp; hp.x = h0; hp.y = h1;
                __nv_bfloat162 lp; lp.x = l0; lp.y = l1;
                *reinterpret_cast<__nv_bfloat162*>(Hi + (size_t)rr * NN + col) = hp;
                *reinterpret_cast<__nv_bfloat162*>(Lo + (size_t)rr * NN + col) = lp;
            }
        }
}

// out[c][m] = (sum_n v[c][n]*at[m][n]) * rscale[m]
__global__ __launch_bounds__(256, 2) void out_mma_kernel(float* __restrict__ out)
{
    extern __shared__ char smem[];
    const uint32_t sb = smem_to_u32(smem);
    const int b = blockIdx.z;
    const int m0 = blockIdx.x * 128;
    const int c0 = blockIdx.y * 128;
    const __nv_bfloat16* vH = g_v_hi + (size_t)b * CC * NN + (size_t)c0 * NN;
    const __nv_bfloat16* vL = g_v_lo + (size_t)b * CC * NN + (size_t)c0 * NN;
    const __nv_bfloat16* aH = g_at_hi + (size_t)b * NN * NN + (size_t)m0 * NN;
    const __nv_bfloat16* aL = g_at_lo + (size_t)b * NN * NN + (size_t)m0 * NN;

    float acc[4][4][4];
    mma_compute(sb, vH, vL, NN, aH, aL, NN, NN, acc);

    const int lane = threadIdx.x & 31;
    const int wid = threadIdx.x >> 5;
    const int wm = wid >> 2, wn = wid & 3;
    const int r0 = wm * 64 + (lane >> 2);
    const int c0l = wn * 32 + (lane & 3) * 2;
    const float* colscale = g_rscale + (size_t)b * NN + m0;
    float* D = out + (size_t)b * CC * NN + (size_t)c0 * NN + m0;
#pragma unroll
    for (int mt = 0; mt < 4; mt++)
#pragma unroll
        for (int nt = 0; nt < 4; nt++) {
            const int row = r0 + mt * 16;
            const int col = c0l + nt * 8;
            const float s0 = colscale[col], s1 = colscale[col + 1];
            *reinterpret_cast<float2*>(D + (size_t)row * NN + col) =
                make_float2(acc[mt][nt][0] * s0, acc[mt][nt][1] * s1);
            *reinterpret_cast<float2*>(D + (size_t)(row + 8) * NN + col) =
                make_float2(acc[mt][nt][2] * s0, acc[mt][nt][3] * s1);
        }
}

// ---------------------------------------------------------------------------
// Elementwise kernels
// ---------------------------------------------------------------------------

__global__ __launch_bounds__(256) void split_w_kernel(
    const float* __restrict__ Wqk, const float* __restrict__ Wv)
{
    const int o = blockIdx.x;
    const int c = threadIdx.x;
    const int idx = o * CC + c;
    if (blockIdx.y == 0) {
        split_bf16(Wqk[idx], g_wqk_hi[idx], g_wqk_lo[idx]);
    } else {
        split_bf16(Wv[idx], g_wv_hi[idx], g_wv_lo[idx]);
    }
}

// transpose + split x: xt[n][c] = x[c][n]. 64x64 tiles.
__global__ __launch_bounds__(256) void split_x_kernel(const float* __restrict__ x)
{
    __shared__ float t[64][65];
    const int b = blockIdx.z;
    const int c0 = blockIdx.x * 64;
    const int n0 = blockIdx.y * 64;
    const float* X = x + (size_t)b * CC * NN;

    const int r = threadIdx.x >> 4;
    const int c4 = (threadIdx.x & 15) * 4;

#pragma unroll
    for (int rr = 0; rr < 4; rr++) {
        const int row = r + rr * 16;
        float4 v = *reinterpret_cast<const float4*>(X + (size_t)(c0 + row) * NN + n0 + c4);
        t[row][c4 + 0] = v.x;
        t[row][c4 + 1] = v.y;
        t[row][c4 + 2] = v.z;
        t[row][c4 + 3] = v.w;
    }
    __syncthreads();

    const size_t ob = (size_t)b * NN * CC;
#pragma unroll
    for (int rr = 0; rr < 4; rr++) {
        const int row = r + rr * 16;
        __align__(8) __nv_bfloat16 hi4[4], lo4[4];
#pragma unroll
        for (int q = 0; q < 4; q++) split_bf16(t[c4 + q][row], hi4[q], lo4[q]);
        const size_t off = ob + (size_t)(n0 + row) * CC + c0 + c4;
        *reinterpret_cast<uint2*>(g_xt_hi + off) = *reinterpret_cast<uint2*>(hi4);
        *reinterpret_cast<uint2*>(g_xt_lo + off) = *reinterpret_cast<uint2*>(lo4);
    }
}

// row softmax over S (in place). One block per row.
__global__ __launch_bounds__(256) void softmax_kernel()
{
    const int tid = threadIdx.x;
    float* __restrict__ row = g_s + ((size_t)blockIdx.y * NN + blockIdx.x) * NN;

    __shared__ float red[8];

    float v[8];
    float mx = -1e30f;
#pragma unroll
    for (int i = 0; i < 8; i++) {
        v[i] = row[i * 256 + tid];
        mx = fmaxf(mx, v[i]);
    }
#pragma unroll
    for (int o = 16; o; o >>= 1) mx = fmaxf(mx, __shfl_xor_sync(0xffffffffu, mx, o));
    if ((tid & 31) == 0) red[tid >> 5] = mx;
    __syncthreads();
    mx = red[0];
#pragma unroll
    for (int i = 1; i < 8; i++) mx = fmaxf(mx, red[i]);
    __syncthreads();

    float s = 0.f;
#pragma unroll
    for (int i = 0; i < 8; i++) {
        v[i] = __expf(v[i] - mx);
        s += v[i];
    }
#pragma unroll
    for (int o = 16; o; o >>= 1) s += __shfl_xor_sync(0xffffffffu, s, o);
    if ((tid & 31) == 0) red[tid >> 5] = s;
    __syncthreads();
    s = red[0];
#pragma unroll
    for (int i = 1; i < 8; i++) s += red[i];

    const float inv = 1.f / s;
#pragma unroll
    for (int i = 0; i < 8; i++) row[i * 256 + tid] = v[i] * inv;
}

// zero colsums (deterministic per launch)
__global__ __launch_bounds__(256) void zero_colsum_kernel()
{
    g_colsum[blockIdx.x * 256 + threadIdx.x] = 0.f;
}

// transpose + bf16 split: at[m][n] = softmax(S)[n][m]; also accumulates
// column sums (over n) into g_colsum via one atomicAdd per (tile, m).
__global__ __launch_bounds__(256) void transpose_split_kernel()
{
    __shared__ float t[64][65];
    const int b = blockIdx.z;
    const int m0 = blockIdx.x * 64;
    const int n0 = blockIdx.y * 64;
    const float* S = g_s + (size_t)b * NN * NN;

    const int tid = threadIdx.x;
    const int lane = tid & 31;
    const int r = tid >> 4;
    const int c4 = (tid & 15) * 4;

#pragma unroll
    for (int rr = 0; rr < 4; rr++) {
        const int row = r + rr * 16;   // n - n0
        float4 v = *reinterpret_cast<const float4*>(S + (size_t)(n0 + row) * NN + m0 + c4);
        t[row][c4 + 0] = v.x;
        t[row][c4 + 1] = v.y;
        t[row][c4 + 2] = v.z;
        t[row][c4 + 3] = v.w;
    }
    __syncthreads();

    const size_t ob = (size_t)b * NN * NN;
#pragma unroll
    for (int rr = 0; rr < 4; rr++) {
        const int row = r + rr * 16;   // m - m0
        float ps = t[c4 + 0][row] + t[c4 + 1][row] + t[c4 + 2][row] + t[c4 + 3][row];
#pragma unroll
        for (int o = 1; o < 16; o <<= 1) ps += __shfl_xor_sync(0xffffffffu, ps, o);
        if ((lane & 15) == 0) atomicAdd(&g_colsum[b * NN + m0 + row], ps);

        __align__(8) __nv_bfloat16 hi4[4], lo4[4];
#pragma unroll
        for (int q = 0; q < 4; q++) split_bf16(t[c4 + q][row], hi4[q], lo4[q]);
        const size_t off = ob + (size_t)(m0 + row) * NN + n0 + c4;
        *reinterpret_cast<uint2*>(g_at_hi + off) = *reinterpret_cast<uint2*>(hi4);
        *reinterpret_cast<uint2*>(g_at_lo + off) = *reinterpret_cast<uint2*>(lo4);
    }
}

__global__ __launch_bounds__(256) void rscale_kernel()
{
    const int i = blockIdx.x * 256 + threadIdx.x;
    g_rscale[i] = 1.0f / ((1e-9f + g_colsum[i]) * 16.0f);
}

// ---------------------------------------------------------------------------
extern "C" void kernel_launch(void* const* d_in, const int* in_sizes, int n_in,
                              void* d_out, int out_size)
{
    const float* x   = (const float*)d_in[0];
    const float* Wqk = (const float*)d_in[1];
    const float* Wv  = (const float*)d_in[2];
    const float* bv  = (const float*)d_in[3];
    float* out = (float*)d_out;

    cudaFuncSetAttribute(energy_mma_kernel, cudaFuncAttributeMaxDynamicSharedMemorySize, SMEM_MMA);
    cudaFuncSetAttribute(out_mma_kernel, cudaFuncAttributeMaxDynamicSharedMemorySize, SMEM_MMA);
    cudaFuncSetAttribute(proj_y_mma_kernel, cudaFuncAttributeMaxDynamicSharedMemorySize, SMEM_MMA);
    cudaFuncSetAttribute(proj_v_mma_kernel, cudaFuncAttributeMaxDynamicSharedMemorySize, SMEM_MMA);

    split_w_kernel<<<dim3(CC, 2), 256>>>(Wqk, Wv);
    split_x_kernel<<<dim3(CC / 64, NN / 64, BB), 256>>>(x);

    proj_y_mma_kernel<<<dim3(CC / 128, NN / 128, BB), 256, SMEM_MMA>>>();
    proj_v_mma_kernel<<<dim3(NN / 128, CC / 128, BB), 256, SMEM_MMA>>>(bv);

    energy_mma_kernel<<<dim3(136, 1, BB), 256, SMEM_MMA>>>();

    zero_colsum_kernel<<<BB * NN / 256, 256>>>();

    softmax_kernel<<<dim3(NN, BB), 256>>>();

    transpose_split_kernel<<<dim3(NN / 64, NN / 64, BB), 256>>>();

    rscale_kernel<<<BB * NN / 256, 256>>>();

    out_mma_kernel<<<dim3(NN / 128, CC / 128, BB), 256, SMEM_MMA>>>(out);
}

// round 8
// speedup vs baseline: 2.6825x; 1.0377x over previous
#include <cuda_runtime.h>
#include <cuda_bf16.h>
#include <cstdint>

#define BB 16
#define CC 256
#define NN 2048

// ---------------------------------------------------------------------------
// Scratch (__device__ globals; no allocation allowed)
// ---------------------------------------------------------------------------
__device__ __nv_bfloat16 g_xt_hi[(size_t)BB * NN * CC];  // x^T [b][n][c]
__device__ __nv_bfloat16 g_xt_lo[(size_t)BB * NN * CC];
__device__ __nv_bfloat16 g_wqk_hi[CC * CC];
__device__ __nv_bfloat16 g_wqk_lo[CC * CC];
__device__ __nv_bfloat16 g_wv_hi[CC * CC];
__device__ __nv_bfloat16 g_wv_lo[CC * CC];
__device__ __nv_bfloat16 g_yt_hi[(size_t)BB * NN * CC];  // y^T [b][n][o]
__device__ __nv_bfloat16 g_yt_lo[(size_t)BB * NN * CC];
__device__ __nv_bfloat16 g_v_hi[(size_t)BB * CC * NN];   // v   [b][c][n]
__device__ __nv_bfloat16 g_v_lo[(size_t)BB * CC * NN];
__device__ __nv_bfloat16 g_at_hi[(size_t)BB * NN * NN];  // attention^T [b][m][n]
__device__ __nv_bfloat16 g_at_lo[(size_t)BB * NN * NN];
__device__ float g_s[(size_t)BB * NN * NN];              // energy (raw logits)
__device__ float g_rowmax[BB * NN];                      // row max of logits
__device__ float g_rowinv[BB * NN];                      // 1/sum(exp(logit-max))
__device__ float g_colsum[BB * NN];                      // sum over n of attention[n][m]
__device__ float g_rscale[BB * NN];                      // 1/((1e-9+colsum)*16)

// ---------------------------------------------------------------------------
// Baseline-PTX helpers (no 'a' features)
// ---------------------------------------------------------------------------
__device__ __forceinline__ uint32_t smem_to_u32(const void* smem_ptr) {
    uint32_t addr;
    asm("{ .reg .u64 tmp; cvta.to.shared.u64 tmp, %1; cvt.u32.u64 %0, tmp; }"
        : "=r"(addr) : "l"(smem_ptr));
    return addr;
}

__device__ __forceinline__ void ldsm_x4(uint32_t* r, uint32_t addr) {
    asm volatile("ldmatrix.sync.aligned.m8n8.x4.shared.b16 {%0,%1,%2,%3}, [%4];"
                 : "=r"(r[0]), "=r"(r[1]), "=r"(r[2]), "=r"(r[3]) : "r"(addr));
}

__device__ __forceinline__ void mma_bf16(float* d, const uint32_t* a, const uint32_t* b) {
    asm volatile(
        "mma.sync.aligned.m16n8k16.row.col.f32.bf16.bf16.f32 "
        "{%0,%1,%2,%3},{%4,%5,%6,%7},{%8,%9},{%0,%1,%2,%3};"
        : "+f"(d[0]), "+f"(d[1]), "+f"(d[2]), "+f"(d[3])
        : "r"(a[0]), "r"(a[1]), "r"(a[2]), "r"(a[3]), "r"(b[0]), "r"(b[1]));
}

__device__ __forceinline__ void cp16(uint32_t saddr, const void* g) {
    asm volatile("cp.async.cg.shared.global [%0], [%1], 16;" :: "r"(saddr), "l"(g));
}
__device__ __forceinline__ void cp_commit() {
    asm volatile("cp.async.commit_group;" ::: "memory");
}
template <int N> __device__ __forceinline__ void cp_wait() {
    asm volatile("cp.async.wait_group %0;" :: "n"(N) : "memory");
}

__device__ __forceinline__ void split_bf16(float f, __nv_bfloat16& h, __nv_bfloat16& l) {
    h = __float2bfloat16(f);
    l = __float2bfloat16(f - __bfloat162float(h));
}

// ---------------------------------------------------------------------------
// Warp-MMA GEMM core: acc[128,128] = sum_k (Ah+Al)[r][k]*(Bh+Bl)[c][k]
// NT layout, 256 thr, warp tile 64x32 (2x4 warps). 4-stage cp.async pipeline
// with K=16 stages, ONE __syncthreads per stage. Split-3: AhBh + AhBl + AlBh.
// A-lo uses its own fragment registers (a2) so all 14 ldmatrix can be issued
// before the MMA stream (no WAR serialization between hi/lo passes).
// ---------------------------------------------------------------------------
#define TSTRIDE 48                        // 16 bf16 = 32B payload + 16B pad
#define TILE_BYTES (128 * TSTRIDE)        // 6144
#define STAGE_BYTES (4 * TILE_BYTES)      // 24576: Ah, Al, Bh, Bl
#define NSTAGE 4
#define SMEM_MMA (NSTAGE * STAGE_BYTES)   // 98304

__device__ __forceinline__ void fill_stage(
    uint32_t sb, int stage, int k0,
    const __nv_bfloat16* __restrict__ Ah, const __nv_bfloat16* __restrict__ Al, int sA,
    const __nv_bfloat16* __restrict__ Bh, const __nv_bfloat16* __restrict__ Bl, int sB)
{
    const int tid = threadIdx.x;
    const int row = tid >> 1;             // 0..127
    const int half = tid & 1;             // 0..1 (8 bf16 each)
    const uint32_t s0 = sb + stage * STAGE_BYTES + row * TSTRIDE + half * 16;
    const int go = k0 + half * 8;
    cp16(s0 + 0 * TILE_BYTES, Ah + (size_t)row * sA + go);
    cp16(s0 + 1 * TILE_BYTES, Al + (size_t)row * sA + go);
    cp16(s0 + 2 * TILE_BYTES, Bh + (size_t)row * sB + go);
    cp16(s0 + 3 * TILE_BYTES, Bl + (size_t)row * sB + go);
}

__device__ __forceinline__ void compute_stage(uint32_t sb, int stage, float acc[4][4][4])
{
    const int lane = threadIdx.x & 31;
    const int wid = threadIdx.x >> 5;
    const int wm = wid >> 2;              // 0..1
    const int wn = wid & 3;               // 0..3
    const uint32_t st = sb + stage * STAGE_BYTES;
    const uint32_t laneoff = (uint32_t)((lane & 15) * TSTRIDE + (lane >> 4) * 16);

    uint32_t b_hi[4][2], b_lo[4][2];
#pragma unroll
    for (int np = 0; np < 2; np++) {
        uint32_t bd = st + 2 * TILE_BYTES + (uint32_t)((wn * 32 + np * 16) * TSTRIDE) + laneoff;
        uint32_t r[4], rl[4];
        ldsm_x4(r, bd);
        ldsm_x4(rl, bd + TILE_BYTES);
        b_hi[np * 2 + 0][0] = r[0];  b_hi[np * 2 + 0][1] = r[2];
        b_hi[np * 2 + 1][0] = r[1];  b_hi[np * 2 + 1][1] = r[3];
        b_lo[np * 2 + 0][0] = rl[0]; b_lo[np * 2 + 0][1] = rl[2];
        b_lo[np * 2 + 1][0] = rl[1]; b_lo[np * 2 + 1][1] = rl[3];
    }
    uint32_t a[4][4], a2[4][4];
    // issue ALL fragment loads up front (a2 independent of a: no WAR)
#pragma unroll
    for (int mt = 0; mt < 4; mt++) {
        uint32_t ad = st + (uint32_t)((wm * 64 + mt * 16) * TSTRIDE) + laneoff;
        ldsm_x4(a[mt], ad);
        ldsm_x4(a2[mt], ad + TILE_BYTES);
    }
    // pass 1: A-hi x (B-hi + B-lo)
#pragma unroll
    for (int mt = 0; mt < 4; mt++)
#pragma unroll
        for (int nt = 0; nt < 4; nt++) {
            mma_bf16(acc[mt][nt], a[mt], b_hi[nt]);
            mma_bf16(acc[mt][nt], a[mt], b_lo[nt]);
        }
    // pass 2: A-lo x B-hi
#pragma unroll
    for (int mt = 0; mt < 4; mt++)
#pragma unroll
        for (int nt = 0; nt < 4; nt++)
            mma_bf16(acc[mt][nt], a2[mt], b_hi[nt]);
}

__device__ __forceinline__ void mma_compute(
    uint32_t sb,
    const __nv_bfloat16* Ah, const __nv_bfloat16* Al, int sA,
    const __nv_bfloat16* Bh, const __nv_bfloat16* Bl, int sB,
    int K, float acc[4][4][4])
{
#pragma unroll
    for (int mt = 0; mt < 4; mt++)
#pragma unroll
        for (int nt = 0; nt < 4; nt++)
#pragma unroll
            for (int q = 0; q < 4; q++) acc[mt][nt][q] = 0.f;

    const int S = K / 16;
#pragma unroll
    for (int p = 0; p < NSTAGE - 1; p++) {
        fill_stage(sb, p, p * 16, Ah, Al, sA, Bh, Bl, sB);
        cp_commit();
    }

    for (int s = 0; s < S; s++) {
        cp_wait<NSTAGE - 2>();
        __syncthreads();
        compute_stage(sb, s & (NSTAGE - 1), acc);
        const int f = s + NSTAGE - 1;
        if (f < S)
            fill_stage(sb, f & (NSTAGE - 1), f * 16, Ah, Al, sA, Bh, Bl, sB);
        cp_commit();
    }
}

// ---------------------------------------------------------------------------
// GEMM kernels (all 2-CTA/SM)
// ---------------------------------------------------------------------------

// energy (symmetric): triangular tile enumeration, mirror via smem transpose.
__global__ __launch_bounds__(256, 2) void energy_mma_kernel()
{
    extern __shared__ char smem[];
    const uint32_t sb = smem_to_u32(smem);
    const int b = blockIdx.z;

    int t = blockIdx.x, i = 0, rem = 16;
    while (t >= rem) { t -= rem; i++; rem = 16 - i; }
    const int j = i + t;
    const int n0 = i * 128;
    const int m0 = j * 128;

    const __nv_bfloat16* baseH = g_yt_hi + (size_t)b * NN * CC;
    const __nv_bfloat16* baseL = g_yt_lo + (size_t)b * NN * CC;
    float* Sbase = g_s + (size_t)b * NN * NN;

    float acc[4][4][4];
    mma_compute(sb, baseH + (size_t)n0 * CC, baseL + (size_t)n0 * CC, CC,
                baseH + (size_t)m0 * CC, baseL + (size_t)m0 * CC, CC, CC, acc);

    const int lane = threadIdx.x & 31;
    const int wid = threadIdx.x >> 5;
    const int wm = wid >> 2, wn = wid & 3;
    const int r0 = wm * 64 + (lane >> 2);
    const int c0 = wn * 32 + (lane & 3) * 2;

#pragma unroll
    for (int mt = 0; mt < 4; mt++)
#pragma unroll
        for (int nt = 0; nt < 4; nt++) {
            const int row = r0 + mt * 16;
            const int col = c0 + nt * 8;
            *reinterpret_cast<float2*>(Sbase + (size_t)(n0 + row) * NN + m0 + col) =
                make_float2(acc[mt][nt][0], acc[mt][nt][1]);
            *reinterpret_cast<float2*>(Sbase + (size_t)(n0 + row + 8) * NN + m0 + col) =
                make_float2(acc[mt][nt][2], acc[mt][nt][3]);
        }

    if (i == j) return;

    __syncthreads();
    float* sm = reinterpret_cast<float*>(smem);
#pragma unroll
    for (int mt = 0; mt < 4; mt++)
#pragma unroll
        for (int nt = 0; nt < 4; nt++) {
            const int row = r0 + mt * 16;
            const int col = c0 + nt * 8;
            sm[row * 129 + col] = acc[mt][nt][0];
            sm[row * 129 + col + 1] = acc[mt][nt][1];
            sm[(row + 8) * 129 + col] = acc[mt][nt][2];
            sm[(row + 8) * 129 + col + 1] = acc[mt][nt][3];
        }
    __syncthreads();

#pragma unroll
    for (int iRow = 0; iRow < 16; iRow++) {
        const int p = wid * 16 + iRow;
        const int q = lane * 4;
        float4 v;
        v.x = sm[(q + 0) * 129 + p];
        v.y = sm[(q + 1) * 129 + p];
        v.z = sm[(q + 2) * 129 + p];
        v.w = sm[(q + 3) * 129 + p];
        *reinterpret_cast<float4*>(Sbase + (size_t)(m0 + p) * NN + n0 + q) = v;
    }
}

// projection y^T: D[n][o] = sum_c xt[n][c]*Wqk[o][c], bf16-split epilogue.
__global__ __launch_bounds__(256, 2) void proj_y_mma_kernel()
{
    extern __shared__ char smem[];
    const uint32_t sb = smem_to_u32(smem);
    const int b = blockIdx.z;
    const int o0 = blockIdx.x * 128;
    const int n0 = blockIdx.y * 128;

    const __nv_bfloat16* xtH = g_xt_hi + (size_t)b * NN * CC + (size_t)n0 * CC;
    const __nv_bfloat16* xtL = g_xt_lo + (size_t)b * NN * CC + (size_t)n0 * CC;

    float acc[4][4][4];
    mma_compute(sb, xtH, xtL, CC,
                g_wqk_hi + (size_t)o0 * CC, g_wqk_lo + (size_t)o0 * CC, CC, CC, acc);

    const int lane = threadIdx.x & 31;
    const int wid = threadIdx.x >> 5;
    const int wm = wid >> 2, wn = wid & 3;
    const int r0 = wm * 64 + (lane >> 2);
    const int c0 = wn * 32 + (lane & 3) * 2;

    __nv_bfloat16* Hi = g_yt_hi + (size_t)b * NN * CC + (size_t)n0 * CC + o0;
    __nv_bfloat16* Lo = g_yt_lo + (size_t)b * NN * CC + (size_t)n0 * CC + o0;
#pragma unroll
    for (int mt = 0; mt < 4; mt++)
#pragma unroll
        for (int nt = 0; nt < 4; nt++) {
            const int row = r0 + mt * 16;
            const int col = c0 + nt * 8;
#pragma unroll
            for (int h = 0; h < 2; h++) {
                const int rr = row + h * 8;
                __nv_bfloat16 h0, l0, h1, l1;
                split_bf16(acc[mt][nt][2 * h + 0], h0, l0);
                split_bf16(acc[mt][nt][2 * h + 1], h1, l1);
                __nv_bfloat162 hp; hp.x = h0; hp.y = h1;
                __nv_bfloat162 lp; lp.x = l0; lp.y = l1;
                *reinterpret_cast<__nv_bfloat162*>(Hi + (size_t)rr * CC + col) = hp;
                *reinterpret_cast<__nv_bfloat162*>(Lo + (size_t)rr * CC + col) = lp;
            }
        }
}

// projection v: D[c][n] = sum_k Wv[c][k]*xt[n][k] + bv[c], bf16-split epilogue.
__global__ __launch_bounds__(256, 2) void proj_v_mma_kernel(const float* __restrict__ bv)
{
    extern __shared__ char smem[];
    const uint32_t sb = smem_to_u32(smem);
    const int b = blockIdx.z;
    const int n0 = blockIdx.x * 128;
    const int c0 = blockIdx.y * 128;

    const __nv_bfloat16* xtH = g_xt_hi + (size_t)b * NN * CC + (size_t)n0 * CC;
    const __nv_bfloat16* xtL = g_xt_lo + (size_t)b * NN * CC + (size_t)n0 * CC;

    float acc[4][4][4];
    mma_compute(sb, g_wv_hi + (size_t)c0 * CC, g_wv_lo + (size_t)c0 * CC, CC,
                xtH, xtL, CC, CC, acc);

    const int lane = threadIdx.x & 31;
    const int wid = threadIdx.x >> 5;
    const int wm = wid >> 2, wn = wid & 3;
    const int r0 = wm * 64 + (lane >> 2);
    const int c0l = wn * 32 + (lane & 3) * 2;

    __nv_bfloat16* Hi = g_v_hi + (size_t)b * CC * NN + (size_t)c0 * NN + n0;
    __nv_bfloat16* Lo = g_v_lo + (size_t)b * CC * NN + (size_t)c0 * NN + n0;
    const float* bias = bv + c0;
#pragma unroll
    for (int mt = 0; mt < 4; mt++)
#pragma unroll
        for (int nt = 0; nt < 4; nt++) {
            const int row = r0 + mt * 16;
            const int col = c0l + nt * 8;
#pragma unroll
            for (int h = 0; h < 2; h++) {
                const int rr = row + h * 8;
                const float badd = bias[rr];
                __nv_bfloat16 h0, l0, h1, l1;
                split_bf16(acc[mt][nt][2 * h + 0] + badd, h0, l0);
                split_bf16(acc[mt][nt][2 * h + 1] + badd, h1, l1);
                __nv_bfloat162 hp; hp.x = h0; hp.y = h1;
                __nv_bfloat162 lp; lp.x = l0; lp.y = l1;
                *reinterpret_cast<__nv_bfloat162*>(Hi + (size_t)rr * NN + col) = hp;
                *reinterpret_cast<__nv_bfloat162*>(Lo + (size_t)rr * NN + col) = lp;
            }
        }
}

// out[c][m] = (sum_n v[c][n]*at[m][n]) * rscale[m]
__global__ __launch_bounds__(256, 2) void out_mma_kernel(float* __restrict__ out)
{
    extern __shared__ char smem[];
    const uint32_t sb = smem_to_u32(smem);
    const int b = blockIdx.z;
    const int m0 = blockIdx.x * 128;
    const int c0 = blockIdx.y * 128;
    const __nv_bfloat16* vH = g_v_hi + (size_t)b * CC * NN + (size_t)c0 * NN;
    const __nv_bfloat16* vL = g_v_lo + (size_t)b * CC * NN + (size_t)c0 * NN;
    const __nv_bfloat16* aH = g_at_hi + (size_t)b * NN * NN + (size_t)m0 * NN;
    const __nv_bfloat16* aL = g_at_lo + (size_t)b * NN * NN + (size_t)m0 * NN;

    float acc[4][4][4];
    mma_compute(sb, vH, vL, NN, aH, aL, NN, NN, acc);

    const int lane = threadIdx.x & 31;
    const int wid = threadIdx.x >> 5;
    const int wm = wid >> 2, wn = wid & 3;
    const int r0 = wm * 64 + (lane >> 2);
    const int c0l = wn * 32 + (lane & 3) * 2;
    const float* colscale = g_rscale + (size_t)b * NN + m0;
    float* D = out + (size_t)b * CC * NN + (size_t)c0 * NN + m0;
#pragma unroll
    for (int mt = 0; mt < 4; mt++)
#pragma unroll
        for (int nt = 0; nt < 4; nt++) {
            const int row = r0 + mt * 16;
            const int col = c0l + nt * 8;
            const float s0 = colscale[col], s1 = colscale[col + 1];
            *reinterpret_cast<float2*>(D + (size_t)row * NN + col) =
                make_float2(acc[mt][nt][0] * s0, acc[mt][nt][1] * s1);
            *reinterpret_cast<float2*>(D + (size_t)(row + 8) * NN + col) =
                make_float2(acc[mt][nt][2] * s0, acc[mt][nt][3] * s1);
        }
}

// ---------------------------------------------------------------------------
// Elementwise kernels
// ---------------------------------------------------------------------------

__global__ __launch_bounds__(256) void split_w_kernel(
    const float* __restrict__ Wqk, const float* __restrict__ Wv)
{
    const int o = blockIdx.x;
    const int c = threadIdx.x;
    const int idx = o * CC + c;
    if (blockIdx.y == 0) {
        split_bf16(Wqk[idx], g_wqk_hi[idx], g_wqk_lo[idx]);
    } else {
        split_bf16(Wv[idx], g_wv_hi[idx], g_wv_lo[idx]);
    }
}

// transpose + split x: xt[n][c] = x[c][n]. 64x64 tiles.
__global__ __launch_bounds__(256) void split_x_kernel(const float* __restrict__ x)
{
    __shared__ float t[64][65];
    const int b = blockIdx.z;
    const int c0 = blockIdx.x * 64;
    const int n0 = blockIdx.y * 64;
    const float* X = x + (size_t)b * CC * NN;

    const int r = threadIdx.x >> 4;
    const int c4 = (threadIdx.x & 15) * 4;

#pragma unroll
    for (int rr = 0; rr < 4; rr++) {
        const int row = r + rr * 16;
        float4 v = *reinterpret_cast<const float4*>(X + (size_t)(c0 + row) * NN + n0 + c4);
        t[row][c4 + 0] = v.x;
        t[row][c4 + 1] = v.y;
        t[row][c4 + 2] = v.z;
        t[row][c4 + 3] = v.w;
    }
    __syncthreads();

    const size_t ob = (size_t)b * NN * CC;
#pragma unroll
    for (int rr = 0; rr < 4; rr++) {
        const int row = r + rr * 16;
        __align__(8) __nv_bfloat16 hi4[4], lo4[4];
#pragma unroll
        for (int q = 0; q < 4; q++) split_bf16(t[c4 + q][row], hi4[q], lo4[q]);
        const size_t off = ob + (size_t)(n0 + row) * CC + c0 + c4;
        *reinterpret_cast<uint2*>(g_xt_hi + off) = *reinterpret_cast<uint2*>(hi4);
        *reinterpret_cast<uint2*>(g_xt_lo + off) = *reinterpret_cast<uint2*>(lo4);
    }
}

// row stats: max + 1/sum(exp(v-max)) per logit row. NO write-back of the row.
__global__ __launch_bounds__(256) void rowstat_kernel()
{
    const int tid = threadIdx.x;
    const int rowi = blockIdx.y * NN + blockIdx.x;
    const float* __restrict__ row = g_s + (size_t)rowi * NN;

    __shared__ float red[8];

    float v[8];
    float mx = -1e30f;
#pragma unroll
    for (int i = 0; i < 8; i++) {
        v[i] = row[i * 256 + tid];
        mx = fmaxf(mx, v[i]);
    }
#pragma unroll
    for (int o = 16; o; o >>= 1) mx = fmaxf(mx, __shfl_xor_sync(0xffffffffu, mx, o));
    if ((tid & 31) == 0) red[tid >> 5] = mx;
    __syncthreads();
    mx = red[0];
#pragma unroll
    for (int i = 1; i < 8; i++) mx = fmaxf(mx, red[i]);
    __syncthreads();

    float s = 0.f;
#pragma unroll
    for (int i = 0; i < 8; i++) s += __expf(v[i] - mx);
#pragma unroll
    for (int o = 16; o; o >>= 1) s += __shfl_xor_sync(0xffffffffu, s, o);
    if ((tid & 31) == 0) red[tid >> 5] = s;
    __syncthreads();
    if (tid == 0) {
        float tot = 0.f;
#pragma unroll
        for (int i = 0; i < 8; i++) tot += red[i];
        g_rowmax[rowi] = mx;
        g_rowinv[rowi] = 1.f / tot;
    }
}

// zero colsums (deterministic per launch)
__global__ __launch_bounds__(256) void zero_colsum_kernel()
{
    g_colsum[blockIdx.x * 256 + threadIdx.x] = 0.f;
}

// fused: a[n][m] = exp(S[n][m]-mx[n])*inv[n]; write at[m][n] bf16 hi/lo
// (transposed) and accumulate column sums into g_colsum.
__global__ __launch_bounds__(256) void transpose_split_kernel()
{
    __shared__ float t[64][65];
    const int b = blockIdx.z;
    const int m0 = blockIdx.x * 64;
    const int n0 = blockIdx.y * 64;
    const float* S = g_s + (size_t)b * NN * NN;
    const float* rmx = g_rowmax + (size_t)b * NN;
    const float* rin = g_rowinv + (size_t)b * NN;

    const int tid = threadIdx.x;
    const int lane = tid & 31;
    const int r = tid >> 4;
    const int c4 = (tid & 15) * 4;

#pragma unroll
    for (int rr = 0; rr < 4; rr++) {
        const int row = r + rr * 16;   // n - n0
        const float mx = rmx[n0 + row];
        const float inv = rin[n0 + row];
        float4 v = *reinterpret_cast<const float4*>(S + (size_t)(n0 + row) * NN + m0 + c4);
        t[row][c4 + 0] = __expf(v.x - mx) * inv;
        t[row][c4 + 1] = __expf(v.y - mx) * inv;
        t[row][c4 + 2] = __expf(v.z - mx) * inv;
        t[row][c4 + 3] = __expf(v.w - mx) * inv;
    }
    __syncthreads();

    const size_t ob = (size_t)b * NN * NN;
#pragma unroll
    for (int rr = 0; rr < 4; rr++) {
        const int row = r + rr * 16;   // m - m0
        float ps = t[c4 + 0][row] + t[c4 + 1][row] + t[c4 + 2][row] + t[c4 + 3][row];
#pragma unroll
        for (int o = 1; o < 16; o <<= 1) ps += __shfl_xor_sync(0xffffffffu, ps, o);
        if ((lane & 15) == 0) atomicAdd(&g_colsum[b * NN + m0 + row], ps);

        __align__(8) __nv_bfloat16 hi4[4], lo4[4];
#pragma unroll
        for (int q = 0; q < 4; q++) split_bf16(t[c4 + q][row], hi4[q], lo4[q]);
        const size_t off = ob + (size_t)(m0 + row) * NN + n0 + c4;
        *reinterpret_cast<uint2*>(g_at_hi + off) = *reinterpret_cast<uint2*>(hi4);
        *reinterpret_cast<uint2*>(g_at_lo + off) = *reinterpret_cast<uint2*>(lo4);
    }
}

__global__ __launch_bounds__(256) void rscale_kernel()
{
    const int i = blockIdx.x * 256 + threadIdx.x;
    g_rscale[i] = 1.0f / ((1e-9f + g_colsum[i]) * 16.0f);
}

// ---------------------------------------------------------------------------
extern "C" void kernel_launch(void* const* d_in, const int* in_sizes, int n_in,
                              void* d_out, int out_size)
{
    const float* x   = (const float*)d_in[0];
    const float* Wqk = (const float*)d_in[1];
    const float* Wv  = (const float*)d_in[2];
    const float* bv  = (const float*)d_in[3];
    float* out = (float*)d_out;

    cudaFuncSetAttribute(energy_mma_kernel, cudaFuncAttributeMaxDynamicSharedMemorySize, SMEM_MMA);
    cudaFuncSetAttribute(out_mma_kernel, cudaFuncAttributeMaxDynamicSharedMemorySize, SMEM_MMA);
    cudaFuncSetAttribute(proj_y_mma_kernel, cudaFuncAttributeMaxDynamicSharedMemorySize, SMEM_MMA);
    cudaFuncSetAttribute(proj_v_mma_kernel, cudaFuncAttributeMaxDynamicSharedMemorySize, SMEM_MMA);

    split_w_kernel<<<dim3(CC, 2), 256>>>(Wqk, Wv);
    split_x_kernel<<<dim3(CC / 64, NN / 64, BB), 256>>>(x);

    proj_y_mma_kernel<<<dim3(CC / 128, NN / 128, BB), 256, SMEM_MMA>>>();
    proj_v_mma_kernel<<<dim3(NN / 128, CC / 128, BB), 256, SMEM_MMA>>>(bv);

    energy_mma_kernel<<<dim3(136, 1, BB), 256, SMEM_MMA>>>();

    zero_colsum_kernel<<<BB * NN / 256, 256>>>();

    rowstat_kernel<<<dim3(NN, BB), 256>>>();

    transpose_split_kernel<<<dim3(NN / 64, NN / 64, BB), 256>>>();

    rscale_kernel<<<BB * NN / 256, 256>>>();

    out_mma_kernel<<<dim3(NN / 128, CC / 128, BB), 256, SMEM_MMA>>>(out);
}